// round 6
// baseline (speedup 1.0000x reference)
#include <cuda_runtime.h>
#include <cuda_bf16.h>
#include <cstdint>

// Problem constants (fixed by the dataset)
constexpr int NTOK = 4096;      // B*S = 4*1024
constexpr int E    = 512;
constexpr int C    = 512;
constexpr int H    = 1024;
constexpr int V    = 32000;
constexpr float EPS = 1e-5f;

constexpr int W_ELEMS  = 3 * 2 * H * H;
constexpr int OW_ELEMS = V * C;

// GEMM tiling: 128x128x32 tile, 256 threads, warp tile 64x32 (2x4 warp grid).
// smem row = [hi 64B | lo 64B] = 128B, SW128 swizzle.
constexpr int BM = 128, BN = 128, BK = 32;
constexpr int HALF_T  = BM * 128;                 // 16384 bytes (A or B half-stage)
constexpr int STAGE   = 2 * HALF_T;               // 32768
constexpr int STAGES  = 3;
constexpr int SMEM_SZ = STAGES * STAGE;           // 98304 -> 2 CTAs/SM

// Scratch (allocation-free rule: __device__ globals)
__device__ float g_hbuf[NTOK * H];
__device__ float g_h2[NTOK * H];
__device__ __nv_bfloat16 g_xhi[NTOK * H], g_xlo[NTOK * H];
__device__ __nv_bfloat16 g_yhi[NTOK * H], g_ylo[NTOK * H];
__device__ __nv_bfloat16 g_whi[W_ELEMS],  g_wlo[W_ELEMS];
__device__ __nv_bfloat16 g_owhi[OW_ELEMS], g_owlo[OW_ELEMS];

// ---------------------------------------------------------------------------
// PTX helpers
// ---------------------------------------------------------------------------
__device__ __forceinline__ uint32_t cvta_smem(const void* p) {
    uint32_t a;
    asm("{\n\t.reg .u64 t;\n\tcvta.to.shared.u64 t, %1;\n\tcvt.u32.u64 %0, t;\n\t}"
        : "=r"(a) : "l"(p));
    return a;
}
__device__ __forceinline__ uint32_t swz(uint32_t o) { return o ^ ((o >> 3) & 0x70); }

__device__ __forceinline__ void cp16(uint32_t dst, const void* src) {
    asm volatile("cp.async.cg.shared.global [%0], [%1], 16;" :: "r"(dst), "l"(src));
}
__device__ __forceinline__ void cp_commit() {
    asm volatile("cp.async.commit_group;" ::: "memory");
}

__device__ __forceinline__ void ldsm4(uint32_t* r, uint32_t addr) {
    asm volatile("ldmatrix.sync.aligned.m8n8.x4.shared.b16 {%0,%1,%2,%3}, [%4];"
                 : "=r"(r[0]), "=r"(r[1]), "=r"(r[2]), "=r"(r[3]) : "r"(addr));
}

// non-volatile: pure register math, ptxas free to schedule
__device__ __forceinline__ void mma16816(float* d, const uint32_t* a,
                                         uint32_t b0, uint32_t b1) {
    asm("mma.sync.aligned.m16n8k16.row.col.f32.bf16.bf16.f32 "
        "{%0,%1,%2,%3}, {%4,%5,%6,%7}, {%8,%9}, {%0,%1,%2,%3};"
        : "+f"(d[0]), "+f"(d[1]), "+f"(d[2]), "+f"(d[3])
        : "r"(a[0]), "r"(a[1]), "r"(a[2]), "r"(a[3]), "r"(b0), "r"(b1));
}

__device__ __forceinline__ void split2(float a, float b, uint32_t& hi, uint32_t& lo) {
    __nv_bfloat16 ha = __float2bfloat16_rn(a), hb = __float2bfloat16_rn(b);
    __nv_bfloat16 la = __float2bfloat16_rn(a - __bfloat162float(ha));
    __nv_bfloat16 lb = __float2bfloat16_rn(b - __bfloat162float(hb));
    hi = (uint32_t)__bfloat16_as_ushort(ha) | ((uint32_t)__bfloat16_as_ushort(hb) << 16);
    lo = (uint32_t)__bfloat16_as_ushort(la) | ((uint32_t)__bfloat16_as_ushort(lb) << 16);
}

// ---------------------------------------------------------------------------
// fp32 -> (bf16 hi, bf16 lo) elementwise split (weights)
// ---------------------------------------------------------------------------
__global__ void __launch_bounds__(256) f32_to_bf16pair(
    const float4* __restrict__ src, uint2* __restrict__ hi, uint2* __restrict__ lo, int n4)
{
    const int i = blockIdx.x * 256 + threadIdx.x;
    if (i >= n4) return;
    const float4 x = src[i];
    uint32_t h0, l0, h1, l1;
    split2(x.x, x.y, h0, l0);
    split2(x.z, x.w, h1, l1);
    hi[i] = make_uint2(h0, h1);
    lo[i] = make_uint2(l0, l1);
}

// ---------------------------------------------------------------------------
// LN reduction helper (128 threads = 4 warps)
// ---------------------------------------------------------------------------
__device__ __forceinline__ void block_reduce_2(float& s, float& s2) {
    #pragma unroll
    for (int o = 16; o > 0; o >>= 1) {
        s  += __shfl_xor_sync(0xFFFFFFFFu, s,  o);
        s2 += __shfl_xor_sync(0xFFFFFFFFu, s2, o);
    }
    __shared__ float red[8];
    int wid = threadIdx.x >> 5;
    int lid = threadIdx.x & 31;
    if (lid == 0) { red[wid] = s; red[4 + wid] = s2; }
    __syncthreads();
    s  = red[0] + red[1] + red[2] + red[3];
    s2 = red[4] + red[5] + red[6] + red[7];
}

// ---------------------------------------------------------------------------
// Embedding gather + LN -> hbuf fp32 [0|tok] and x hi/lo bf16 (full row)
// ---------------------------------------------------------------------------
__global__ void __launch_bounds__(128) embed_ln_kernel(
    const int* __restrict__ ids, const float* __restrict__ table,
    const float* __restrict__ g, const float* __restrict__ b)
{
    const int tok = blockIdx.x;
    const int tid = threadIdx.x;
    const long id = ids[tok];

    float4 x = reinterpret_cast<const float4*>(table + id * (long)E)[tid];
    float s  = x.x + x.y + x.z + x.w;
    float s2 = x.x * x.x + x.y * x.y + x.z * x.z + x.w * x.w;
    block_reduce_2(s, s2);

    const float mean = s * (1.0f / E);
    const float var  = s2 * (1.0f / E) - mean * mean;
    const float rstd = rsqrtf(var + EPS);

    float4 gg = reinterpret_cast<const float4*>(g)[tid];
    float4 bb = reinterpret_cast<const float4*>(b)[tid];
    float4 y;
    y.x = (x.x - mean) * rstd * gg.x + bb.x;
    y.y = (x.y - mean) * rstd * gg.y + bb.y;
    y.z = (x.z - mean) * rstd * gg.z + bb.z;
    y.w = (x.w - mean) * rstd * gg.w + bb.w;

    const long rbase = (long)tok * H;
    float* row = g_hbuf + rbase;
    reinterpret_cast<float4*>(row + C)[tid] = y;
    reinterpret_cast<float4*>(row)[tid] = make_float4(0.f, 0.f, 0.f, 0.f);

    uint32_t h0, l0, h1, l1;
    split2(y.x, y.y, h0, l0);
    split2(y.z, y.w, h1, l1);
    reinterpret_cast<uint2*>(g_xhi + rbase + C)[tid] = make_uint2(h0, h1);
    reinterpret_cast<uint2*>(g_xlo + rbase + C)[tid] = make_uint2(l0, l1);
    reinterpret_cast<uint2*>(g_xhi + rbase)[tid] = make_uint2(0, 0);
    reinterpret_cast<uint2*>(g_xlo + rbase)[tid] = make_uint2(0, 0);
}

// ---------------------------------------------------------------------------
// Residual + LN; writes hbuf fp32 and x hi/lo bf16
// ---------------------------------------------------------------------------
__global__ void __launch_bounds__(128) resid_ln_kernel(
    const float* __restrict__ cg, const float* __restrict__ cb,
    const float* __restrict__ tg, const float* __restrict__ tb)
{
    const int tok  = blockIdx.x;
    const int half = blockIdx.y;
    const int tid  = threadIdx.x;
    const float* g  = half ? tg : cg;
    const float* bp = half ? tb : cb;

    const long base = (long)tok * H + half * C;
    float4 a = reinterpret_cast<const float4*>(g_hbuf + base)[tid];
    float4 h = reinterpret_cast<const float4*>(g_h2 + base)[tid];
    float4 x;
    x.x = a.x + h.x; x.y = a.y + h.y; x.z = a.z + h.z; x.w = a.w + h.w;

    float s  = x.x + x.y + x.z + x.w;
    float s2 = x.x * x.x + x.y * x.y + x.z * x.z + x.w * x.w;
    block_reduce_2(s, s2);

    const float mean = s * (1.0f / C);
    const float var  = s2 * (1.0f / C) - mean * mean;
    const float rstd = rsqrtf(var + EPS);

    float4 gg = reinterpret_cast<const float4*>(g)[tid];
    float4 bb = reinterpret_cast<const float4*>(bp)[tid];
    float4 y;
    y.x = (x.x - mean) * rstd * gg.x + bb.x;
    y.y = (x.y - mean) * rstd * gg.y + bb.y;
    y.z = (x.z - mean) * rstd * gg.z + bb.z;
    y.w = (x.w - mean) * rstd * gg.w + bb.w;
    reinterpret_cast<float4*>(g_hbuf + base)[tid] = y;

    uint32_t h0, l0, h1, l1;
    split2(y.x, y.y, h0, l0);
    split2(y.z, y.w, h1, l1);
    reinterpret_cast<uint2*>(g_xhi + base)[tid] = make_uint2(h0, h1);
    reinterpret_cast<uint2*>(g_xlo + base)[tid] = make_uint2(l0, l1);
}

// ---------------------------------------------------------------------------
// bf16x3 split GEMM on mma.sync: D[M,N] = A[M,K] @ B[N,K]^T + bias
// BK=32, 3-stage cp.async pipeline, 96KB smem -> 2 CTAs/SM (4 warps/SMSP).
// smem row (128B) = [hi 64B | lo 64B], SW128 swizzle.
// OUT_MODE 0: fp32 out. OUT_MODE 1: bf16 hi/lo out.
// ---------------------------------------------------------------------------
template <bool RELU, int OUT_MODE>
__global__ void __launch_bounds__(256, 2) gemm_mma(
    const __nv_bfloat16* __restrict__ Ahi, const __nv_bfloat16* __restrict__ Alo, int lda,
    const __nv_bfloat16* __restrict__ Bhi, const __nv_bfloat16* __restrict__ Blo, int ldb,
    const float* __restrict__ bias,
    float* __restrict__ Cf,
    __nv_bfloat16* __restrict__ Chi, __nv_bfloat16* __restrict__ Clo,
    int ldc, int K)
{
    extern __shared__ char smem[];
    const uint32_t sb = cvta_smem(smem);
    const int tid = threadIdx.x;
    const int w   = tid >> 5;
    const int l   = tid & 31;
    const int wm  = (w >> 2) * 64;
    const int wn  = (w & 3) * 32;
    const long m0 = (long)blockIdx.y * BM;
    const long n0 = (long)blockIdx.x * BN;

    const int lrow  = ((l >> 3) & 1) * 8 + (l & 7);
    const int lkseg = ((l >> 4) & 1) * 16;

    const int NC = K >> 5;              // chunks of BK=32

    // loader: 8 cp16 per thread per chunk (A 4, B 4)
    const int ldrow = tid >> 3;         // plus it*32
    const int ldcol = tid & 7;          // 16B column within 128B row
    auto load_chunk = [&](int c, int stage) {
        const int k0 = c << 5;
        const uint32_t sbase = sb + (uint32_t)stage * STAGE;
        #pragma unroll
        for (int it = 0; it < 4; ++it) {
            const int r = it * 32 + ldrow;
            const uint32_t so = swz((uint32_t)(r * 128 + ldcol * 16));
            const __nv_bfloat16* srcA = (ldcol < 4)
                ? Ahi + (m0 + r) * (long)lda + k0 + ldcol * 8
                : Alo + (m0 + r) * (long)lda + k0 + (ldcol - 4) * 8;
            cp16(sbase + so, srcA);
            const __nv_bfloat16* srcB = (ldcol < 4)
                ? Bhi + (n0 + r) * (long)ldb + k0 + ldcol * 8
                : Blo + (n0 + r) * (long)ldb + k0 + (ldcol - 4) * 8;
            cp16(sbase + HALF_T + so, srcB);
        }
    };

    float acc[4][4][4];
    #pragma unroll
    for (int i = 0; i < 4; ++i)
        #pragma unroll
        for (int j = 0; j < 4; ++j)
            #pragma unroll
            for (int q = 0; q < 4; ++q) acc[i][j][q] = 0.0f;

    // single-buffered fragments (48 regs) — occupancy covers the latency
    uint32_t Ah[4][4], Al[4][4], Bh[2][4], Bl[2][4];

    auto ld_frag = [&](uint32_t sbase, int j) {
        const int kb = j * 32 + lkseg;        // hi bytes; lo at +64
        #pragma unroll
        for (int mf = 0; mf < 4; ++mf) {
            const uint32_t rbase = (uint32_t)((wm + mf * 16 + lrow) * 128);
            ldsm4(Ah[mf], sbase + swz(rbase + kb));
            ldsm4(Al[mf], sbase + swz(rbase + 64 + kb));
        }
        #pragma unroll
        for (int nf2 = 0; nf2 < 2; ++nf2) {
            const uint32_t rbase = (uint32_t)((wn + nf2 * 16 + lrow) * 128);
            ldsm4(Bh[nf2], sbase + HALF_T + swz(rbase + kb));
            ldsm4(Bl[nf2], sbase + HALF_T + swz(rbase + 64 + kb));
        }
    };
    // split-major: dependent MMAs on one accumulator are 16 apart
    auto mma_all = [&]() {
        #pragma unroll
        for (int mf = 0; mf < 4; ++mf)
            #pragma unroll
            for (int nf = 0; nf < 4; ++nf) {
                const int p = nf >> 1, q = nf & 1;
                mma16816(acc[mf][nf], Ah[mf], Bh[p][q], Bh[p][q + 2]);
            }
        #pragma unroll
        for (int mf = 0; mf < 4; ++mf)
            #pragma unroll
            for (int nf = 0; nf < 4; ++nf) {
                const int p = nf >> 1, q = nf & 1;
                mma16816(acc[mf][nf], Ah[mf], Bl[p][q], Bl[p][q + 2]);
            }
        #pragma unroll
        for (int mf = 0; mf < 4; ++mf)
            #pragma unroll
            for (int nf = 0; nf < 4; ++nf) {
                const int p = nf >> 1, q = nf & 1;
                mma16816(acc[mf][nf], Al[mf], Bh[p][q], Bh[p][q + 2]);
            }
    };

    load_chunk(0, 0); cp_commit();
    load_chunk(1, 1); cp_commit();

    for (int c = 0; c < NC; ++c) {
        if (c + 1 < NC) asm volatile("cp.async.wait_group 1;" ::: "memory");
        else            asm volatile("cp.async.wait_group 0;" ::: "memory");
        __syncthreads();

        const uint32_t sbase = sb + (uint32_t)(c % STAGES) * STAGE;
        const int cn = c + 2;

        ld_frag(sbase, 0);
        mma_all();
        if (cn < NC) { load_chunk(cn, cn % STAGES); cp_commit(); }
        ld_frag(sbase, 1);
        mma_all();
        // stage-reuse safety: writes for chunk c+2 target stage (c+2)%3,
        // which was last read in iteration c-1; the barrier at the top of
        // this iteration proves all warps left it.
    }

    // Epilogue
    const int tig = l & 3, grp = l >> 2;
    #pragma unroll
    for (int nf = 0; nf < 4; ++nf) {
        const long col = n0 + wn + nf * 8 + 2 * tig;
        const float b0 = bias[col], b1 = bias[col + 1];
        #pragma unroll
        for (int mf = 0; mf < 4; ++mf) {
            const long r0 = m0 + wm + mf * 16 + grp;
            float v00 = acc[mf][nf][0] + b0, v01 = acc[mf][nf][1] + b1;
            float v10 = acc[mf][nf][2] + b0, v11 = acc[mf][nf][3] + b1;
            if (RELU) {
                v00 = fmaxf(v00, 0.f); v01 = fmaxf(v01, 0.f);
                v10 = fmaxf(v10, 0.f); v11 = fmaxf(v11, 0.f);
            }
            if (OUT_MODE == 0) {
                *reinterpret_cast<float2*>(Cf + r0 * (long)ldc + col) = make_float2(v00, v01);
                *reinterpret_cast<float2*>(Cf + (r0 + 8) * (long)ldc + col) = make_float2(v10, v11);
            } else {
                uint32_t h0, lo0, h1, lo1;
                split2(v00, v01, h0, lo0);
                split2(v10, v11, h1, lo1);
                *reinterpret_cast<uint32_t*>(Chi + r0 * (long)ldc + col) = h0;
                *reinterpret_cast<uint32_t*>(Clo + r0 * (long)ldc + col) = lo0;
                *reinterpret_cast<uint32_t*>(Chi + (r0 + 8) * (long)ldc + col) = h1;
                *reinterpret_cast<uint32_t*>(Clo + (r0 + 8) * (long)ldc + col) = lo1;
            }
        }
    }
}

// ---------------------------------------------------------------------------
// Launch
// ---------------------------------------------------------------------------
extern "C" void kernel_launch(void* const* d_in, const int* in_sizes, int n_in,
                              void* d_out, int out_size)
{
    const int*   ids   = (const int*)  d_in[0];
    const float* table = (const float*)d_in[1];
    const float* en_g  = (const float*)d_in[2];
    const float* en_b  = (const float*)d_in[3];
    const float* Wb    = (const float*)d_in[4];
    const float* bb    = (const float*)d_in[5];
    const float* cn_g  = (const float*)d_in[6];
    const float* cn_b  = (const float*)d_in[7];
    const float* tn_g  = (const float*)d_in[8];
    const float* tn_b  = (const float*)d_in[9];
    const float* out_W = (const float*)d_in[10];
    const float* out_b = (const float*)d_in[11];
    float* logits = (float*)d_out;

    __nv_bfloat16 *xhi, *xlo, *yhi, *ylo, *whi, *wlo, *owhi, *owlo;
    float *h2;
    cudaGetSymbolAddress((void**)&xhi,  g_xhi);
    cudaGetSymbolAddress((void**)&xlo,  g_xlo);
    cudaGetSymbolAddress((void**)&yhi,  g_yhi);
    cudaGetSymbolAddress((void**)&ylo,  g_ylo);
    cudaGetSymbolAddress((void**)&whi,  g_whi);
    cudaGetSymbolAddress((void**)&wlo,  g_wlo);
    cudaGetSymbolAddress((void**)&owhi, g_owhi);
    cudaGetSymbolAddress((void**)&owlo, g_owlo);
    cudaGetSymbolAddress((void**)&h2,   g_h2);

    cudaFuncSetAttribute(gemm_mma<true, 1>,  cudaFuncAttributeMaxDynamicSharedMemorySize, SMEM_SZ);
    cudaFuncSetAttribute(gemm_mma<true, 0>,  cudaFuncAttributeMaxDynamicSharedMemorySize, SMEM_SZ);
    cudaFuncSetAttribute(gemm_mma<false, 0>, cudaFuncAttributeMaxDynamicSharedMemorySize, SMEM_SZ);

    // 1) split weights into bf16 hi/lo
    f32_to_bf16pair<<<W_ELEMS / 4 / 256, 256>>>(
        (const float4*)Wb, (uint2*)whi, (uint2*)wlo, W_ELEMS / 4);
    f32_to_bf16pair<<<OW_ELEMS / 4 / 256, 256>>>(
        (const float4*)out_W, (uint2*)owhi, (uint2*)owlo, OW_ELEMS / 4);

    // 2) embedding + LN
    embed_ln_kernel<<<NTOK, 128>>>(ids, table, en_g, en_b);

    // 3) three residual blocks
    const dim3 fnn_grid(H / BN, NTOK / BM);           // (8, 32)
    for (int bi = 0; bi < 3; ++bi) {
        const __nv_bfloat16* W0h = whi + (long)(bi * 2 + 0) * H * H;
        const __nv_bfloat16* W0l = wlo + (long)(bi * 2 + 0) * H * H;
        const __nv_bfloat16* W1h = whi + (long)(bi * 2 + 1) * H * H;
        const __nv_bfloat16* W1l = wlo + (long)(bi * 2 + 1) * H * H;
        const float* b0 = bb + (bi * 2 + 0) * H;
        const float* b1 = bb + (bi * 2 + 1) * H;

        gemm_mma<true, 1><<<fnn_grid, 256, SMEM_SZ>>>(
            xhi, xlo, H, W0h, W0l, H, b0,
            (float*)nullptr, yhi, ylo, H, H);
        gemm_mma<true, 0><<<fnn_grid, 256, SMEM_SZ>>>(
            yhi, ylo, H, W1h, W1l, H, b1,
            h2, (__nv_bfloat16*)nullptr, (__nv_bfloat16*)nullptr, H, H);
        resid_ln_kernel<<<dim3(NTOK, 2), 128>>>(cn_g + bi * C, cn_b + bi * C,
                                                tn_g + bi * E, tn_b + bi * E);
    }

    // 4) logits = tok @ out_W^T + out_b
    const dim3 out_grid(V / BN, NTOK / BM);           // (250, 32)
    gemm_mma<false, 0><<<out_grid, 256, SMEM_SZ>>>(
        xhi + C, xlo + C, H, owhi, owlo, C, out_b,
        logits, (__nv_bfloat16*)nullptr, (__nv_bfloat16*)nullptr, V, C);
}

// round 7
// speedup vs baseline: 1.2824x; 1.2824x over previous
#include <cuda_runtime.h>
#include <cuda_bf16.h>
#include <cuda_fp16.h>
#include <cstdint>

// Problem constants (fixed by the dataset)
constexpr int NTOK = 4096;      // B*S = 4*1024
constexpr int E    = 512;
constexpr int C    = 512;
constexpr int H    = 1024;
constexpr int V    = 32000;
constexpr float EPS = 1e-5f;

constexpr int W_ELEMS  = 3 * 2 * H * H;
constexpr int OW_ELEMS = V * C;

// FNN GEMM tiling (R4/R5 best config): 128x128x64, 256 threads, warp 64x32
constexpr int BM = 128, BN = 128, BK = 64;
constexpr int TILE_B  = BM * BK * 2;              // 16384 bytes per split tile
constexpr int STAGE   = 4 * TILE_B;               // Ahi|Alo|Bhi|Blo = 65536
constexpr int STAGES  = 3;
constexpr int SMEM_SZ = STAGES * STAGE;           // 196608

// Logits GEMM (fp16 2-term): tiles Ahi|Alo|B, 3 stages
constexpr int L_TILE   = BM * BK * 2;             // 16384
constexpr int L_STAGE  = 3 * L_TILE;              // 49152
constexpr int L_SMEM   = STAGES * L_STAGE;        // 147456

// Scratch (allocation-free rule: __device__ globals)
__device__ float g_hbuf[NTOK * H];
__device__ float g_h2[NTOK * H];
__device__ __nv_bfloat16 g_xhi[NTOK * H], g_xlo[NTOK * H];
__device__ __nv_bfloat16 g_yhi[NTOK * H], g_ylo[NTOK * H];
__device__ __nv_bfloat16 g_whi[W_ELEMS],  g_wlo[W_ELEMS];
__device__ __half g_th[NTOK * E], g_tl[NTOK * E];   // tok fp16 hi/lo (logits A)
__device__ __half g_owh[OW_ELEMS];                  // out_W fp16 (logits B)

// ---------------------------------------------------------------------------
// PTX helpers
// ---------------------------------------------------------------------------
__device__ __forceinline__ uint32_t cvta_smem(const void* p) {
    uint32_t a;
    asm("{\n\t.reg .u64 t;\n\tcvta.to.shared.u64 t, %1;\n\tcvt.u32.u64 %0, t;\n\t}"
        : "=r"(a) : "l"(p));
    return a;
}
__device__ __forceinline__ uint32_t swz(uint32_t o) { return o ^ ((o >> 3) & 0x70); }

__device__ __forceinline__ void cp16(uint32_t dst, const void* src) {
    asm volatile("cp.async.cg.shared.global [%0], [%1], 16;" :: "r"(dst), "l"(src));
}
__device__ __forceinline__ void cp_commit() {
    asm volatile("cp.async.commit_group;" ::: "memory");
}

__device__ __forceinline__ void ldsm4(uint32_t* r, uint32_t addr) {
    asm volatile("ldmatrix.sync.aligned.m8n8.x4.shared.b16 {%0,%1,%2,%3}, [%4];"
                 : "=r"(r[0]), "=r"(r[1]), "=r"(r[2]), "=r"(r[3]) : "r"(addr));
}

__device__ __forceinline__ void mma16816(float* d, const uint32_t* a,
                                         uint32_t b0, uint32_t b1) {
    asm("mma.sync.aligned.m16n8k16.row.col.f32.bf16.bf16.f32 "
        "{%0,%1,%2,%3}, {%4,%5,%6,%7}, {%8,%9}, {%0,%1,%2,%3};"
        : "+f"(d[0]), "+f"(d[1]), "+f"(d[2]), "+f"(d[3])
        : "r"(a[0]), "r"(a[1]), "r"(a[2]), "r"(a[3]), "r"(b0), "r"(b1));
}
__device__ __forceinline__ void mma16816h(float* d, const uint32_t* a,
                                          uint32_t b0, uint32_t b1) {
    asm("mma.sync.aligned.m16n8k16.row.col.f32.f16.f16.f32 "
        "{%0,%1,%2,%3}, {%4,%5,%6,%7}, {%8,%9}, {%0,%1,%2,%3};"
        : "+f"(d[0]), "+f"(d[1]), "+f"(d[2]), "+f"(d[3])
        : "r"(a[0]), "r"(a[1]), "r"(a[2]), "r"(a[3]), "r"(b0), "r"(b1));
}

__device__ __forceinline__ void split2(float a, float b, uint32_t& hi, uint32_t& lo) {
    __nv_bfloat16 ha = __float2bfloat16_rn(a), hb = __float2bfloat16_rn(b);
    __nv_bfloat16 la = __float2bfloat16_rn(a - __bfloat162float(ha));
    __nv_bfloat16 lb = __float2bfloat16_rn(b - __bfloat162float(hb));
    hi = (uint32_t)__bfloat16_as_ushort(ha) | ((uint32_t)__bfloat16_as_ushort(hb) << 16);
    lo = (uint32_t)__bfloat16_as_ushort(la) | ((uint32_t)__bfloat16_as_ushort(lb) << 16);
}
__device__ __forceinline__ void split2h(float a, float b, uint32_t& hi, uint32_t& lo) {
    __half ha = __float2half_rn(a), hb = __float2half_rn(b);
    __half la = __float2half_rn(a - __half2float(ha));
    __half lb = __float2half_rn(b - __half2float(hb));
    hi = (uint32_t)__half_as_ushort(ha) | ((uint32_t)__half_as_ushort(hb) << 16);
    lo = (uint32_t)__half_as_ushort(la) | ((uint32_t)__half_as_ushort(lb) << 16);
}

// ---------------------------------------------------------------------------
// fp32 -> (bf16 hi, bf16 lo) elementwise split (FNN weights)
// ---------------------------------------------------------------------------
__global__ void __launch_bounds__(256) f32_to_bf16pair(
    const float4* __restrict__ src, uint2* __restrict__ hi, uint2* __restrict__ lo, int n4)
{
    const int i = blockIdx.x * 256 + threadIdx.x;
    if (i >= n4) return;
    const float4 x = src[i];
    uint32_t h0, l0, h1, l1;
    split2(x.x, x.y, h0, l0);
    split2(x.z, x.w, h1, l1);
    hi[i] = make_uint2(h0, h1);
    lo[i] = make_uint2(l0, l1);
}

// fp32 -> fp16 single (out_W)
__global__ void __launch_bounds__(256) f32_to_f16(
    const float4* __restrict__ src, uint2* __restrict__ dst, int n4)
{
    const int i = blockIdx.x * 256 + threadIdx.x;
    if (i >= n4) return;
    const float4 x = src[i];
    uint32_t a = (uint32_t)__half_as_ushort(__float2half_rn(x.x)) |
                 ((uint32_t)__half_as_ushort(__float2half_rn(x.y)) << 16);
    uint32_t b = (uint32_t)__half_as_ushort(__float2half_rn(x.z)) |
                 ((uint32_t)__half_as_ushort(__float2half_rn(x.w)) << 16);
    dst[i] = make_uint2(a, b);
}

// tok fp32 (hbuf[:, C:]) -> fp16 hi/lo compact [NTOK, E]
__global__ void __launch_bounds__(128) tok_split_f16()
{
    const int tok = blockIdx.x;
    const int tid = threadIdx.x;
    float4 x = reinterpret_cast<const float4*>(g_hbuf + (long)tok * H + C)[tid];
    uint32_t h0, l0, h1, l1;
    split2h(x.x, x.y, h0, l0);
    split2h(x.z, x.w, h1, l1);
    reinterpret_cast<uint2*>(g_th + (long)tok * E)[tid] = make_uint2(h0, h1);
    reinterpret_cast<uint2*>(g_tl + (long)tok * E)[tid] = make_uint2(l0, l1);
}

// ---------------------------------------------------------------------------
// LN reduction helper (128 threads = 4 warps)
// ---------------------------------------------------------------------------
__device__ __forceinline__ void block_reduce_2(float& s, float& s2) {
    #pragma unroll
    for (int o = 16; o > 0; o >>= 1) {
        s  += __shfl_xor_sync(0xFFFFFFFFu, s,  o);
        s2 += __shfl_xor_sync(0xFFFFFFFFu, s2, o);
    }
    __shared__ float red[8];
    int wid = threadIdx.x >> 5;
    int lid = threadIdx.x & 31;
    if (lid == 0) { red[wid] = s; red[4 + wid] = s2; }
    __syncthreads();
    s  = red[0] + red[1] + red[2] + red[3];
    s2 = red[4] + red[5] + red[6] + red[7];
}

// ---------------------------------------------------------------------------
// Embedding gather + LN -> hbuf fp32 [0|tok] and x hi/lo bf16 (full row)
// ---------------------------------------------------------------------------
__global__ void __launch_bounds__(128) embed_ln_kernel(
    const int* __restrict__ ids, const float* __restrict__ table,
    const float* __restrict__ g, const float* __restrict__ b)
{
    const int tok = blockIdx.x;
    const int tid = threadIdx.x;
    const long id = ids[tok];

    float4 x = reinterpret_cast<const float4*>(table + id * (long)E)[tid];
    float s  = x.x + x.y + x.z + x.w;
    float s2 = x.x * x.x + x.y * x.y + x.z * x.z + x.w * x.w;
    block_reduce_2(s, s2);

    const float mean = s * (1.0f / E);
    const float var  = s2 * (1.0f / E) - mean * mean;
    const float rstd = rsqrtf(var + EPS);

    float4 gg = reinterpret_cast<const float4*>(g)[tid];
    float4 bb = reinterpret_cast<const float4*>(b)[tid];
    float4 y;
    y.x = (x.x - mean) * rstd * gg.x + bb.x;
    y.y = (x.y - mean) * rstd * gg.y + bb.y;
    y.z = (x.z - mean) * rstd * gg.z + bb.z;
    y.w = (x.w - mean) * rstd * gg.w + bb.w;

    const long rbase = (long)tok * H;
    float* row = g_hbuf + rbase;
    reinterpret_cast<float4*>(row + C)[tid] = y;
    reinterpret_cast<float4*>(row)[tid] = make_float4(0.f, 0.f, 0.f, 0.f);

    uint32_t h0, l0, h1, l1;
    split2(y.x, y.y, h0, l0);
    split2(y.z, y.w, h1, l1);
    reinterpret_cast<uint2*>(g_xhi + rbase + C)[tid] = make_uint2(h0, h1);
    reinterpret_cast<uint2*>(g_xlo + rbase + C)[tid] = make_uint2(l0, l1);
    reinterpret_cast<uint2*>(g_xhi + rbase)[tid] = make_uint2(0, 0);
    reinterpret_cast<uint2*>(g_xlo + rbase)[tid] = make_uint2(0, 0);
}

// ---------------------------------------------------------------------------
// Residual + LN; writes hbuf fp32 and x hi/lo bf16
// ---------------------------------------------------------------------------
__global__ void __launch_bounds__(128) resid_ln_kernel(
    const float* __restrict__ cg, const float* __restrict__ cb,
    const float* __restrict__ tg, const float* __restrict__ tb)
{
    const int tok  = blockIdx.x;
    const int half = blockIdx.y;
    const int tid  = threadIdx.x;
    const float* g  = half ? tg : cg;
    const float* bp = half ? tb : cb;

    const long base = (long)tok * H + half * C;
    float4 a = reinterpret_cast<const float4*>(g_hbuf + base)[tid];
    float4 h = reinterpret_cast<const float4*>(g_h2 + base)[tid];
    float4 x;
    x.x = a.x + h.x; x.y = a.y + h.y; x.z = a.z + h.z; x.w = a.w + h.w;

    float s  = x.x + x.y + x.z + x.w;
    float s2 = x.x * x.x + x.y * x.y + x.z * x.z + x.w * x.w;
    block_reduce_2(s, s2);

    const float mean = s * (1.0f / C);
    const float var  = s2 * (1.0f / C) - mean * mean;
    const float rstd = rsqrtf(var + EPS);

    float4 gg = reinterpret_cast<const float4*>(g)[tid];
    float4 bb = reinterpret_cast<const float4*>(bp)[tid];
    float4 y;
    y.x = (x.x - mean) * rstd * gg.x + bb.x;
    y.y = (x.y - mean) * rstd * gg.y + bb.y;
    y.z = (x.z - mean) * rstd * gg.z + bb.z;
    y.w = (x.w - mean) * rstd * gg.w + bb.w;
    reinterpret_cast<float4*>(g_hbuf + base)[tid] = y;

    uint32_t h0, l0, h1, l1;
    split2(y.x, y.y, h0, l0);
    split2(y.z, y.w, h1, l1);
    reinterpret_cast<uint2*>(g_xhi + base)[tid] = make_uint2(h0, h1);
    reinterpret_cast<uint2*>(g_xlo + base)[tid] = make_uint2(l0, l1);
}

// ---------------------------------------------------------------------------
// FNN GEMM: bf16x3 split on mma.sync (R4/R5 best config, unchanged)
// OUT_MODE 0: fp32 out. OUT_MODE 1: bf16 hi/lo out.
// ---------------------------------------------------------------------------
template <bool RELU, int OUT_MODE>
__global__ void __launch_bounds__(256, 1) gemm_mma(
    const __nv_bfloat16* __restrict__ Ahi, const __nv_bfloat16* __restrict__ Alo, int lda,
    const __nv_bfloat16* __restrict__ Bhi, const __nv_bfloat16* __restrict__ Blo, int ldb,
    const float* __restrict__ bias,
    float* __restrict__ Cf,
    __nv_bfloat16* __restrict__ Chi, __nv_bfloat16* __restrict__ Clo,
    int ldc, int K)
{
    extern __shared__ char smem[];
    const uint32_t sb = cvta_smem(smem);
    const int tid = threadIdx.x;
    const int w   = tid >> 5;
    const int l   = tid & 31;
    const int wm  = (w >> 2) * 64;
    const int wn  = (w & 3) * 32;
    const long m0 = (long)blockIdx.y * BM;
    const long n0 = (long)blockIdx.x * BN;

    const int lrow  = ((l >> 3) & 1) * 8 + (l & 7);
    const int lkseg = ((l >> 4) & 1) * 16;

    const int NC = K >> 6;

    const int ldr  = tid >> 3;
    const int ldc8 = (tid & 7) * 8;

    auto load_part = [&](int c, uint32_t sbase, int it) {
        const int k0 = c << 6;
        const int r = it * 32 + ldr;
        const uint32_t so = swz((uint32_t)(r * 128) + (uint32_t)((tid & 7) * 16));
        const long ga = (m0 + r) * (long)lda + k0 + ldc8;
        const long gb = (n0 + r) * (long)ldb + k0 + ldc8;
        cp16(sbase + so,              Ahi + ga);
        cp16(sbase + TILE_B + so,     Alo + ga);
        cp16(sbase + 2 * TILE_B + so, Bhi + gb);
        cp16(sbase + 3 * TILE_B + so, Blo + gb);
    };
    auto load_chunk = [&](int c, int stage) {
        const uint32_t sbase = sb + (uint32_t)stage * STAGE;
        #pragma unroll
        for (int it = 0; it < 4; ++it) load_part(c, sbase, it);
    };

    float acc[4][4][4];
    #pragma unroll
    for (int i = 0; i < 4; ++i)
        #pragma unroll
        for (int j = 0; j < 4; ++j)
            #pragma unroll
            for (int q = 0; q < 4; ++q) acc[i][j][q] = 0.0f;

    uint32_t Ah[2][4][4], Al[2][4][4], Bh[2][2][4], Bl[2][2][4];

    auto ld_frag = [&](int buf, uint32_t sbase, int ks) {
        const int kb = ks * 32 + lkseg;
        #pragma unroll
        for (int mf = 0; mf < 4; ++mf) {
            const uint32_t off = swz((uint32_t)((wm + mf * 16 + lrow) * 128 + kb));
            ldsm4(Ah[buf][mf], sbase + off);
            ldsm4(Al[buf][mf], sbase + TILE_B + off);
        }
        #pragma unroll
        for (int nf2 = 0; nf2 < 2; ++nf2) {
            const uint32_t off = swz((uint32_t)((wn + nf2 * 16 + lrow) * 128 + kb));
            ldsm4(Bh[buf][nf2], sbase + 2 * TILE_B + off);
            ldsm4(Bl[buf][nf2], sbase + 3 * TILE_B + off);
        }
    };
    auto mma_all = [&](int buf) {
        #pragma unroll
        for (int mf = 0; mf < 4; ++mf)
            #pragma unroll
            for (int nf = 0; nf < 4; ++nf) {
                const int p = nf >> 1, q = nf & 1;
                mma16816(acc[mf][nf], Ah[buf][mf], Bh[buf][p][q], Bh[buf][p][q + 2]);
            }
        #pragma unroll
        for (int mf = 0; mf < 4; ++mf)
            #pragma unroll
            for (int nf = 0; nf < 4; ++nf) {
                const int p = nf >> 1, q = nf & 1;
                mma16816(acc[mf][nf], Ah[buf][mf], Bl[buf][p][q], Bl[buf][p][q + 2]);
            }
        #pragma unroll
        for (int mf = 0; mf < 4; ++mf)
            #pragma unroll
            for (int nf = 0; nf < 4; ++nf) {
                const int p = nf >> 1, q = nf & 1;
                mma16816(acc[mf][nf], Al[buf][mf], Bh[buf][p][q], Bh[buf][p][q + 2]);
            }
    };

    load_chunk(0, 0); cp_commit();
    if (NC > 1) { load_chunk(1, 1); cp_commit(); }

    for (int c = 0; c < NC; ++c) {
        if (c + 1 < NC) asm volatile("cp.async.wait_group 1;" ::: "memory");
        else            asm volatile("cp.async.wait_group 0;" ::: "memory");
        __syncthreads();

        const uint32_t sbase = sb + (uint32_t)(c % STAGES) * STAGE;
        const int cn = c + 2;
        const uint32_t nbase = sb + (uint32_t)(cn % STAGES) * STAGE;
        const bool has_next = cn < NC;

        ld_frag(0, sbase, 0);
        #pragma unroll
        for (int ks = 0; ks < 4; ++ks) {
            if (ks < 3) ld_frag((ks + 1) & 1, sbase, ks + 1);
            if (has_next) load_part(cn, nbase, ks);
            mma_all(ks & 1);
        }
        if (has_next) cp_commit();
    }

    const int tig = l & 3, grp = l >> 2;
    #pragma unroll
    for (int nf = 0; nf < 4; ++nf) {
        const long col = n0 + wn + nf * 8 + 2 * tig;
        const float b0 = bias[col], b1 = bias[col + 1];
        #pragma unroll
        for (int mf = 0; mf < 4; ++mf) {
            const long r0 = m0 + wm + mf * 16 + grp;
            float v00 = acc[mf][nf][0] + b0, v01 = acc[mf][nf][1] + b1;
            float v10 = acc[mf][nf][2] + b0, v11 = acc[mf][nf][3] + b1;
            if (RELU) {
                v00 = fmaxf(v00, 0.f); v01 = fmaxf(v01, 0.f);
                v10 = fmaxf(v10, 0.f); v11 = fmaxf(v11, 0.f);
            }
            if (OUT_MODE == 0) {
                *reinterpret_cast<float2*>(Cf + r0 * (long)ldc + col) = make_float2(v00, v01);
                *reinterpret_cast<float2*>(Cf + (r0 + 8) * (long)ldc + col) = make_float2(v10, v11);
            } else {
                uint32_t h0, lo0, h1, lo1;
                split2(v00, v01, h0, lo0);
                split2(v10, v11, h1, lo1);
                *reinterpret_cast<uint32_t*>(Chi + r0 * (long)ldc + col) = h0;
                *reinterpret_cast<uint32_t*>(Clo + r0 * (long)ldc + col) = lo0;
                *reinterpret_cast<uint32_t*>(Chi + (r0 + 8) * (long)ldc + col) = h1;
                *reinterpret_cast<uint32_t*>(Clo + (r0 + 8) * (long)ldc + col) = lo1;
            }
        }
    }
}

// ---------------------------------------------------------------------------
// Logits GEMM: fp16 2-term. D = (Ah + Al) @ B^T + bias, fp32 accumulate.
// A = tok split fp16 (hi/lo, 22-bit effective), B = out_W single fp16.
// Error source: B fp16 rounding only (~2.8e-4 RMS rel).
// ---------------------------------------------------------------------------
__global__ void __launch_bounds__(256, 1) gemm_f16x2(
    const __half* __restrict__ Ahi, const __half* __restrict__ Alo, int lda,
    const __half* __restrict__ B, int ldb,
    const float* __restrict__ bias,
    float* __restrict__ Cf, int ldc, int K)
{
    extern __shared__ char smem[];
    const uint32_t sb = cvta_smem(smem);
    const int tid = threadIdx.x;
    const int w   = tid >> 5;
    const int l   = tid & 31;
    const int wm  = (w >> 2) * 64;
    const int wn  = (w & 3) * 32;
    const long m0 = (long)blockIdx.y * BM;
    const long n0 = (long)blockIdx.x * BN;

    const int lrow  = ((l >> 3) & 1) * 8 + (l & 7);
    const int lkseg = ((l >> 4) & 1) * 16;

    const int NC = K >> 6;

    const int ldr  = tid >> 3;
    const int ldc8 = (tid & 7) * 8;

    auto load_part = [&](int c, uint32_t sbase, int it) {
        const int k0 = c << 6;
        const int r = it * 32 + ldr;
        const uint32_t so = swz((uint32_t)(r * 128) + (uint32_t)((tid & 7) * 16));
        const long ga = (m0 + r) * (long)lda + k0 + ldc8;
        const long gb = (n0 + r) * (long)ldb + k0 + ldc8;
        cp16(sbase + so,              Ahi + ga);
        cp16(sbase + L_TILE + so,     Alo + ga);
        cp16(sbase + 2 * L_TILE + so, B + gb);
    };
    auto load_chunk = [&](int c, int stage) {
        const uint32_t sbase = sb + (uint32_t)stage * L_STAGE;
        #pragma unroll
        for (int it = 0; it < 4; ++it) load_part(c, sbase, it);
    };

    float acc[4][4][4];
    #pragma unroll
    for (int i = 0; i < 4; ++i)
        #pragma unroll
        for (int j = 0; j < 4; ++j)
            #pragma unroll
            for (int q = 0; q < 4; ++q) acc[i][j][q] = 0.0f;

    uint32_t Ah[2][4][4], Al[2][4][4], Bf[2][2][4];

    auto ld_frag = [&](int buf, uint32_t sbase, int ks) {
        const int kb = ks * 32 + lkseg;
        #pragma unroll
        for (int mf = 0; mf < 4; ++mf) {
            const uint32_t off = swz((uint32_t)((wm + mf * 16 + lrow) * 128 + kb));
            ldsm4(Ah[buf][mf], sbase + off);
            ldsm4(Al[buf][mf], sbase + L_TILE + off);
        }
        #pragma unroll
        for (int nf2 = 0; nf2 < 2; ++nf2) {
            const uint32_t off = swz((uint32_t)((wn + nf2 * 16 + lrow) * 128 + kb));
            ldsm4(Bf[buf][nf2], sbase + 2 * L_TILE + off);
        }
    };
    auto mma_all = [&](int buf) {
        #pragma unroll
        for (int mf = 0; mf < 4; ++mf)
            #pragma unroll
            for (int nf = 0; nf < 4; ++nf) {
                const int p = nf >> 1, q = nf & 1;
                mma16816h(acc[mf][nf], Ah[buf][mf], Bf[buf][p][q], Bf[buf][p][q + 2]);
            }
        #pragma unroll
        for (int mf = 0; mf < 4; ++mf)
            #pragma unroll
            for (int nf = 0; nf < 4; ++nf) {
                const int p = nf >> 1, q = nf & 1;
                mma16816h(acc[mf][nf], Al[buf][mf], Bf[buf][p][q], Bf[buf][p][q + 2]);
            }
    };

    load_chunk(0, 0); cp_commit();
    load_chunk(1, 1); cp_commit();

    for (int c = 0; c < NC; ++c) {
        if (c + 1 < NC) asm volatile("cp.async.wait_group 1;" ::: "memory");
        else            asm volatile("cp.async.wait_group 0;" ::: "memory");
        __syncthreads();

        const uint32_t sbase = sb + (uint32_t)(c % STAGES) * L_STAGE;
        const int cn = c + 2;
        const uint32_t nbase = sb + (uint32_t)(cn % STAGES) * L_STAGE;
        const bool has_next = cn < NC;

        ld_frag(0, sbase, 0);
        #pragma unroll
        for (int ks = 0; ks < 4; ++ks) {
            if (ks < 3) ld_frag((ks + 1) & 1, sbase, ks + 1);
            if (has_next) load_part(cn, nbase, ks);
            mma_all(ks & 1);
        }
        if (has_next) cp_commit();
    }

    const int tig = l & 3, grp = l >> 2;
    #pragma unroll
    for (int nf = 0; nf < 4; ++nf) {
        const long col = n0 + wn + nf * 8 + 2 * tig;
        const float b0 = bias[col], b1 = bias[col + 1];
        #pragma unroll
        for (int mf = 0; mf < 4; ++mf) {
            const long r0 = m0 + wm + mf * 16 + grp;
            *reinterpret_cast<float2*>(Cf + r0 * (long)ldc + col) =
                make_float2(acc[mf][nf][0] + b0, acc[mf][nf][1] + b1);
            *reinterpret_cast<float2*>(Cf + (r0 + 8) * (long)ldc + col) =
                make_float2(acc[mf][nf][2] + b0, acc[mf][nf][3] + b1);
        }
    }
}

// ---------------------------------------------------------------------------
// Launch
// ---------------------------------------------------------------------------
extern "C" void kernel_launch(void* const* d_in, const int* in_sizes, int n_in,
                              void* d_out, int out_size)
{
    const int*   ids   = (const int*)  d_in[0];
    const float* table = (const float*)d_in[1];
    const float* en_g  = (const float*)d_in[2];
    const float* en_b  = (const float*)d_in[3];
    const float* Wb    = (const float*)d_in[4];
    const float* bb    = (const float*)d_in[5];
    const float* cn_g  = (const float*)d_in[6];
    const float* cn_b  = (const float*)d_in[7];
    const float* tn_g  = (const float*)d_in[8];
    const float* tn_b  = (const float*)d_in[9];
    const float* out_W = (const float*)d_in[10];
    const float* out_b = (const float*)d_in[11];
    float* logits = (float*)d_out;

    __nv_bfloat16 *xhi, *xlo, *yhi, *ylo, *whi, *wlo;
    __half *th, *tl, *owh;
    float *h2;
    cudaGetSymbolAddress((void**)&xhi,  g_xhi);
    cudaGetSymbolAddress((void**)&xlo,  g_xlo);
    cudaGetSymbolAddress((void**)&yhi,  g_yhi);
    cudaGetSymbolAddress((void**)&ylo,  g_ylo);
    cudaGetSymbolAddress((void**)&whi,  g_whi);
    cudaGetSymbolAddress((void**)&wlo,  g_wlo);
    cudaGetSymbolAddress((void**)&th,   g_th);
    cudaGetSymbolAddress((void**)&tl,   g_tl);
    cudaGetSymbolAddress((void**)&owh,  g_owh);
    cudaGetSymbolAddress((void**)&h2,   g_h2);

    cudaFuncSetAttribute(gemm_mma<true, 1>,  cudaFuncAttributeMaxDynamicSharedMemorySize, SMEM_SZ);
    cudaFuncSetAttribute(gemm_mma<true, 0>,  cudaFuncAttributeMaxDynamicSharedMemorySize, SMEM_SZ);
    cudaFuncSetAttribute(gemm_f16x2,         cudaFuncAttributeMaxDynamicSharedMemorySize, L_SMEM);

    // 1) split FNN weights bf16 hi/lo; out_W -> fp16
    f32_to_bf16pair<<<W_ELEMS / 4 / 256, 256>>>(
        (const float4*)Wb, (uint2*)whi, (uint2*)wlo, W_ELEMS / 4);
    f32_to_f16<<<OW_ELEMS / 4 / 256, 256>>>(
        (const float4*)out_W, (uint2*)owh, OW_ELEMS / 4);

    // 2) embedding + LN
    embed_ln_kernel<<<NTOK, 128>>>(ids, table, en_g, en_b);

    // 3) three residual blocks (bf16x3 FNN)
    const dim3 fnn_grid(H / BN, NTOK / BM);           // (8, 32)
    for (int bi = 0; bi < 3; ++bi) {
        const __nv_bfloat16* W0h = whi + (long)(bi * 2 + 0) * H * H;
        const __nv_bfloat16* W0l = wlo + (long)(bi * 2 + 0) * H * H;
        const __nv_bfloat16* W1h = whi + (long)(bi * 2 + 1) * H * H;
        const __nv_bfloat16* W1l = wlo + (long)(bi * 2 + 1) * H * H;
        const float* b0 = bb + (bi * 2 + 0) * H;
        const float* b1 = bb + (bi * 2 + 1) * H;

        gemm_mma<true, 1><<<fnn_grid, 256, SMEM_SZ>>>(
            xhi, xlo, H, W0h, W0l, H, b0,
            (float*)nullptr, yhi, ylo, H, H);
        gemm_mma<true, 0><<<fnn_grid, 256, SMEM_SZ>>>(
            yhi, ylo, H, W1h, W1l, H, b1,
            h2, (__nv_bfloat16*)nullptr, (__nv_bfloat16*)nullptr, H, H);
        resid_ln_kernel<<<dim3(NTOK, 2), 128>>>(cn_g + bi * C, cn_b + bi * C,
                                                tn_g + bi * E, tn_b + bi * E);
    }

    // 4) tok -> fp16 hi/lo, then logits = tok @ out_W^T + out_b (fp16 2-term)
    tok_split_f16<<<NTOK, 128>>>();
    const dim3 out_grid(V / BN, NTOK / BM);           // (250, 32)
    gemm_f16x2<<<out_grid, 256, L_SMEM>>>(
        th, tl, E, owh, C, out_b, logits, V, C);
}

// round 8
// speedup vs baseline: 1.6785x; 1.3089x over previous
#include <cuda_runtime.h>
#include <cuda_bf16.h>
#include <cuda_fp16.h>
#include <cstdint>

// Problem constants (fixed by the dataset)
constexpr int NTOK = 4096;      // B*S = 4*1024
constexpr int E    = 512;
constexpr int C    = 512;
constexpr int H    = 1024;
constexpr int V    = 32000;
constexpr float EPS = 1e-5f;

constexpr int W_ELEMS  = 3 * 2 * H * H;
constexpr int OW_ELEMS = V * C;

// FNN GEMM tiling: 128x128x64, 256 threads, warp 64x32
constexpr int BM = 128, BN = 128, BK = 64;
constexpr int TILE_B  = BM * BK * 2;              // 16384 bytes per split tile
constexpr int STAGE   = 4 * TILE_B;               // Ahi|Alo|Bhi|Blo = 65536
constexpr int STAGES  = 3;
constexpr int SMEM_SZ = STAGES * STAGE;           // 196608

// Logits GEMM (fp16 1-term): tiles A|B per stage
constexpr int L_TILE   = BM * BK * 2;             // 16384
constexpr int L_STAGE  = 2 * L_TILE;              // 32768
constexpr int L_SMEM   = STAGES * L_STAGE;        // 98304

// Scratch (allocation-free rule: __device__ globals)
__device__ float g_hbuf[NTOK * H];
__device__ float g_h2[NTOK * H];
__device__ __nv_bfloat16 g_xhi[NTOK * H], g_xlo[NTOK * H];
__device__ __nv_bfloat16 g_yhi[NTOK * H], g_ylo[NTOK * H];
__device__ __nv_bfloat16 g_whi[W_ELEMS],  g_wlo[W_ELEMS];
__device__ __half g_th[NTOK * E];                   // tok fp16 (logits A)
__device__ __half g_owh[OW_ELEMS];                  // out_W fp16 (logits B)

// ---------------------------------------------------------------------------
// PTX helpers
// ---------------------------------------------------------------------------
__device__ __forceinline__ uint32_t cvta_smem(const void* p) {
    uint32_t a;
    asm("{\n\t.reg .u64 t;\n\tcvta.to.shared.u64 t, %1;\n\tcvt.u32.u64 %0, t;\n\t}"
        : "=r"(a) : "l"(p));
    return a;
}
__device__ __forceinline__ uint32_t swz(uint32_t o) { return o ^ ((o >> 3) & 0x70); }

__device__ __forceinline__ void cp16(uint32_t dst, const void* src) {
    asm volatile("cp.async.cg.shared.global [%0], [%1], 16;" :: "r"(dst), "l"(src));
}
__device__ __forceinline__ void cp_commit() {
    asm volatile("cp.async.commit_group;" ::: "memory");
}

__device__ __forceinline__ void ldsm4(uint32_t* r, uint32_t addr) {
    asm volatile("ldmatrix.sync.aligned.m8n8.x4.shared.b16 {%0,%1,%2,%3}, [%4];"
                 : "=r"(r[0]), "=r"(r[1]), "=r"(r[2]), "=r"(r[3]) : "r"(addr));
}

__device__ __forceinline__ void mma16816(float* d, const uint32_t* a,
                                         uint32_t b0, uint32_t b1) {
    asm("mma.sync.aligned.m16n8k16.row.col.f32.bf16.bf16.f32 "
        "{%0,%1,%2,%3}, {%4,%5,%6,%7}, {%8,%9}, {%0,%1,%2,%3};"
        : "+f"(d[0]), "+f"(d[1]), "+f"(d[2]), "+f"(d[3])
        : "r"(a[0]), "r"(a[1]), "r"(a[2]), "r"(a[3]), "r"(b0), "r"(b1));
}
__device__ __forceinline__ void mma16816h(float* d, const uint32_t* a,
                                          uint32_t b0, uint32_t b1) {
    asm("mma.sync.aligned.m16n8k16.row.col.f32.f16.f16.f32 "
        "{%0,%1,%2,%3}, {%4,%5,%6,%7}, {%8,%9}, {%0,%1,%2,%3};"
        : "+f"(d[0]), "+f"(d[1]), "+f"(d[2]), "+f"(d[3])
        : "r"(a[0]), "r"(a[1]), "r"(a[2]), "r"(a[3]), "r"(b0), "r"(b1));
}

__device__ __forceinline__ void split2(float a, float b, uint32_t& hi, uint32_t& lo) {
    __nv_bfloat16 ha = __float2bfloat16_rn(a), hb = __float2bfloat16_rn(b);
    __nv_bfloat16 la = __float2bfloat16_rn(a - __bfloat162float(ha));
    __nv_bfloat16 lb = __float2bfloat16_rn(b - __bfloat162float(hb));
    hi = (uint32_t)__bfloat16_as_ushort(ha) | ((uint32_t)__bfloat16_as_ushort(hb) << 16);
    lo = (uint32_t)__bfloat16_as_ushort(la) | ((uint32_t)__bfloat16_as_ushort(lb) << 16);
}

// ---------------------------------------------------------------------------
// fp32 -> (bf16 hi, bf16 lo) elementwise split (FNN weights)
// ---------------------------------------------------------------------------
__global__ void __launch_bounds__(256) f32_to_bf16pair(
    const float4* __restrict__ src, uint2* __restrict__ hi, uint2* __restrict__ lo, int n4)
{
    const int i = blockIdx.x * 256 + threadIdx.x;
    if (i >= n4) return;
    const float4 x = src[i];
    uint32_t h0, l0, h1, l1;
    split2(x.x, x.y, h0, l0);
    split2(x.z, x.w, h1, l1);
    hi[i] = make_uint2(h0, h1);
    lo[i] = make_uint2(l0, l1);
}

// fp32 -> fp16 single (out_W)
__global__ void __launch_bounds__(256) f32_to_f16(
    const float4* __restrict__ src, uint2* __restrict__ dst, int n4)
{
    const int i = blockIdx.x * 256 + threadIdx.x;
    if (i >= n4) return;
    const float4 x = src[i];
    uint32_t a = (uint32_t)__half_as_ushort(__float2half_rn(x.x)) |
                 ((uint32_t)__half_as_ushort(__float2half_rn(x.y)) << 16);
    uint32_t b = (uint32_t)__half_as_ushort(__float2half_rn(x.z)) |
                 ((uint32_t)__half_as_ushort(__float2half_rn(x.w)) << 16);
    dst[i] = make_uint2(a, b);
}

// tok fp32 (hbuf[:, C:]) -> fp16 compact [NTOK, E]
__global__ void __launch_bounds__(128) tok_to_f16()
{
    const int tok = blockIdx.x;
    const int tid = threadIdx.x;
    float4 x = reinterpret_cast<const float4*>(g_hbuf + (long)tok * H + C)[tid];
    uint32_t a = (uint32_t)__half_as_ushort(__float2half_rn(x.x)) |
                 ((uint32_t)__half_as_ushort(__float2half_rn(x.y)) << 16);
    uint32_t b = (uint32_t)__half_as_ushort(__float2half_rn(x.z)) |
                 ((uint32_t)__half_as_ushort(__float2half_rn(x.w)) << 16);
    reinterpret_cast<uint2*>(g_th + (long)tok * E)[tid] = make_uint2(a, b);
}

// ---------------------------------------------------------------------------
// LN reduction helper (128 threads = 4 warps)
// ---------------------------------------------------------------------------
__device__ __forceinline__ void block_reduce_2(float& s, float& s2) {
    #pragma unroll
    for (int o = 16; o > 0; o >>= 1) {
        s  += __shfl_xor_sync(0xFFFFFFFFu, s,  o);
        s2 += __shfl_xor_sync(0xFFFFFFFFu, s2, o);
    }
    __shared__ float red[8];
    int wid = threadIdx.x >> 5;
    int lid = threadIdx.x & 31;
    if (lid == 0) { red[wid] = s; red[4 + wid] = s2; }
    __syncthreads();
    s  = red[0] + red[1] + red[2] + red[3];
    s2 = red[4] + red[5] + red[6] + red[7];
}

// ---------------------------------------------------------------------------
// Embedding gather + LN -> hbuf fp32 [0|tok] and x hi/lo bf16 (full row)
// ---------------------------------------------------------------------------
__global__ void __launch_bounds__(128) embed_ln_kernel(
    const int* __restrict__ ids, const float* __restrict__ table,
    const float* __restrict__ g, const float* __restrict__ b)
{
    const int tok = blockIdx.x;
    const int tid = threadIdx.x;
    const long id = ids[tok];

    float4 x = reinterpret_cast<const float4*>(table + id * (long)E)[tid];
    float s  = x.x + x.y + x.z + x.w;
    float s2 = x.x * x.x + x.y * x.y + x.z * x.z + x.w * x.w;
    block_reduce_2(s, s2);

    const float mean = s * (1.0f / E);
    const float var  = s2 * (1.0f / E) - mean * mean;
    const float rstd = rsqrtf(var + EPS);

    float4 gg = reinterpret_cast<const float4*>(g)[tid];
    float4 bb = reinterpret_cast<const float4*>(b)[tid];
    float4 y;
    y.x = (x.x - mean) * rstd * gg.x + bb.x;
    y.y = (x.y - mean) * rstd * gg.y + bb.y;
    y.z = (x.z - mean) * rstd * gg.z + bb.z;
    y.w = (x.w - mean) * rstd * gg.w + bb.w;

    const long rbase = (long)tok * H;
    float* row = g_hbuf + rbase;
    reinterpret_cast<float4*>(row + C)[tid] = y;
    reinterpret_cast<float4*>(row)[tid] = make_float4(0.f, 0.f, 0.f, 0.f);

    uint32_t h0, l0, h1, l1;
    split2(y.x, y.y, h0, l0);
    split2(y.z, y.w, h1, l1);
    reinterpret_cast<uint2*>(g_xhi + rbase + C)[tid] = make_uint2(h0, h1);
    reinterpret_cast<uint2*>(g_xlo + rbase + C)[tid] = make_uint2(l0, l1);
    reinterpret_cast<uint2*>(g_xhi + rbase)[tid] = make_uint2(0, 0);
    reinterpret_cast<uint2*>(g_xlo + rbase)[tid] = make_uint2(0, 0);
}

// ---------------------------------------------------------------------------
// Residual + LN; writes hbuf fp32 and x hi/lo bf16
// ---------------------------------------------------------------------------
__global__ void __launch_bounds__(128) resid_ln_kernel(
    const float* __restrict__ cg, const float* __restrict__ cb,
    const float* __restrict__ tg, const float* __restrict__ tb)
{
    const int tok  = blockIdx.x;
    const int half = blockIdx.y;
    const int tid  = threadIdx.x;
    const float* g  = half ? tg : cg;
    const float* bp = half ? tb : cb;

    const long base = (long)tok * H + half * C;
    float4 a = reinterpret_cast<const float4*>(g_hbuf + base)[tid];
    float4 h = reinterpret_cast<const float4*>(g_h2 + base)[tid];
    float4 x;
    x.x = a.x + h.x; x.y = a.y + h.y; x.z = a.z + h.z; x.w = a.w + h.w;

    float s  = x.x + x.y + x.z + x.w;
    float s2 = x.x * x.x + x.y * x.y + x.z * x.z + x.w * x.w;
    block_reduce_2(s, s2);

    const float mean = s * (1.0f / C);
    const float var  = s2 * (1.0f / C) - mean * mean;
    const float rstd = rsqrtf(var + EPS);

    float4 gg = reinterpret_cast<const float4*>(g)[tid];
    float4 bb = reinterpret_cast<const float4*>(bp)[tid];
    float4 y;
    y.x = (x.x - mean) * rstd * gg.x + bb.x;
    y.y = (x.y - mean) * rstd * gg.y + bb.y;
    y.z = (x.z - mean) * rstd * gg.z + bb.z;
    y.w = (x.w - mean) * rstd * gg.w + bb.w;
    reinterpret_cast<float4*>(g_hbuf + base)[tid] = y;

    uint32_t h0, l0, h1, l1;
    split2(y.x, y.y, h0, l0);
    split2(y.z, y.w, h1, l1);
    reinterpret_cast<uint2*>(g_xhi + base)[tid] = make_uint2(h0, h1);
    reinterpret_cast<uint2*>(g_xlo + base)[tid] = make_uint2(l0, l1);
}

// ---------------------------------------------------------------------------
// FNN GEMM: bf16x3 split on mma.sync (best config, unchanged)
// OUT_MODE 0: fp32 out. OUT_MODE 1: bf16 hi/lo out.
// ---------------------------------------------------------------------------
template <bool RELU, int OUT_MODE>
__global__ void __launch_bounds__(256, 1) gemm_mma(
    const __nv_bfloat16* __restrict__ Ahi, const __nv_bfloat16* __restrict__ Alo, int lda,
    const __nv_bfloat16* __restrict__ Bhi, const __nv_bfloat16* __restrict__ Blo, int ldb,
    const float* __restrict__ bias,
    float* __restrict__ Cf,
    __nv_bfloat16* __restrict__ Chi, __nv_bfloat16* __restrict__ Clo,
    int ldc, int K)
{
    extern __shared__ char smem[];
    const uint32_t sb = cvta_smem(smem);
    const int tid = threadIdx.x;
    const int w   = tid >> 5;
    const int l   = tid & 31;
    const int wm  = (w >> 2) * 64;
    const int wn  = (w & 3) * 32;
    const long m0 = (long)blockIdx.y * BM;
    const long n0 = (long)blockIdx.x * BN;

    const int lrow  = ((l >> 3) & 1) * 8 + (l & 7);
    const int lkseg = ((l >> 4) & 1) * 16;

    const int NC = K >> 6;

    const int ldr  = tid >> 3;
    const int ldc8 = (tid & 7) * 8;

    auto load_part = [&](int c, uint32_t sbase, int it) {
        const int k0 = c << 6;
        const int r = it * 32 + ldr;
        const uint32_t so = swz((uint32_t)(r * 128) + (uint32_t)((tid & 7) * 16));
        const long ga = (m0 + r) * (long)lda + k0 + ldc8;
        const long gb = (n0 + r) * (long)ldb + k0 + ldc8;
        cp16(sbase + so,              Ahi + ga);
        cp16(sbase + TILE_B + so,     Alo + ga);
        cp16(sbase + 2 * TILE_B + so, Bhi + gb);
        cp16(sbase + 3 * TILE_B + so, Blo + gb);
    };
    auto load_chunk = [&](int c, int stage) {
        const uint32_t sbase = sb + (uint32_t)stage * STAGE;
        #pragma unroll
        for (int it = 0; it < 4; ++it) load_part(c, sbase, it);
    };

    float acc[4][4][4];
    #pragma unroll
    for (int i = 0; i < 4; ++i)
        #pragma unroll
        for (int j = 0; j < 4; ++j)
            #pragma unroll
            for (int q = 0; q < 4; ++q) acc[i][j][q] = 0.0f;

    uint32_t Ah[2][4][4], Al[2][4][4], Bh[2][2][4], Bl[2][2][4];

    auto ld_frag = [&](int buf, uint32_t sbase, int ks) {
        const int kb = ks * 32 + lkseg;
        #pragma unroll
        for (int mf = 0; mf < 4; ++mf) {
            const uint32_t off = swz((uint32_t)((wm + mf * 16 + lrow) * 128 + kb));
            ldsm4(Ah[buf][mf], sbase + off);
            ldsm4(Al[buf][mf], sbase + TILE_B + off);
        }
        #pragma unroll
        for (int nf2 = 0; nf2 < 2; ++nf2) {
            const uint32_t off = swz((uint32_t)((wn + nf2 * 16 + lrow) * 128 + kb));
            ldsm4(Bh[buf][nf2], sbase + 2 * TILE_B + off);
            ldsm4(Bl[buf][nf2], sbase + 3 * TILE_B + off);
        }
    };
    auto mma_all = [&](int buf) {
        #pragma unroll
        for (int mf = 0; mf < 4; ++mf)
            #pragma unroll
            for (int nf = 0; nf < 4; ++nf) {
                const int p = nf >> 1, q = nf & 1;
                mma16816(acc[mf][nf], Ah[buf][mf], Bh[buf][p][q], Bh[buf][p][q + 2]);
            }
        #pragma unroll
        for (int mf = 0; mf < 4; ++mf)
            #pragma unroll
            for (int nf = 0; nf < 4; ++nf) {
                const int p = nf >> 1, q = nf & 1;
                mma16816(acc[mf][nf], Ah[buf][mf], Bl[buf][p][q], Bl[buf][p][q + 2]);
            }
        #pragma unroll
        for (int mf = 0; mf < 4; ++mf)
            #pragma unroll
            for (int nf = 0; nf < 4; ++nf) {
                const int p = nf >> 1, q = nf & 1;
                mma16816(acc[mf][nf], Al[buf][mf], Bh[buf][p][q], Bh[buf][p][q + 2]);
            }
    };

    load_chunk(0, 0); cp_commit();
    if (NC > 1) { load_chunk(1, 1); cp_commit(); }

    for (int c = 0; c < NC; ++c) {
        if (c + 1 < NC) asm volatile("cp.async.wait_group 1;" ::: "memory");
        else            asm volatile("cp.async.wait_group 0;" ::: "memory");
        __syncthreads();

        const uint32_t sbase = sb + (uint32_t)(c % STAGES) * STAGE;
        const int cn = c + 2;
        const uint32_t nbase = sb + (uint32_t)(cn % STAGES) * STAGE;
        const bool has_next = cn < NC;

        ld_frag(0, sbase, 0);
        #pragma unroll
        for (int ks = 0; ks < 4; ++ks) {
            if (ks < 3) ld_frag((ks + 1) & 1, sbase, ks + 1);
            if (has_next) load_part(cn, nbase, ks);
            mma_all(ks & 1);
        }
        if (has_next) cp_commit();
    }

    const int tig = l & 3, grp = l >> 2;
    #pragma unroll
    for (int nf = 0; nf < 4; ++nf) {
        const long col = n0 + wn + nf * 8 + 2 * tig;
        const float b0 = bias[col], b1 = bias[col + 1];
        #pragma unroll
        for (int mf = 0; mf < 4; ++mf) {
            const long r0 = m0 + wm + mf * 16 + grp;
            float v00 = acc[mf][nf][0] + b0, v01 = acc[mf][nf][1] + b1;
            float v10 = acc[mf][nf][2] + b0, v11 = acc[mf][nf][3] + b1;
            if (RELU) {
                v00 = fmaxf(v00, 0.f); v01 = fmaxf(v01, 0.f);
                v10 = fmaxf(v10, 0.f); v11 = fmaxf(v11, 0.f);
            }
            if (OUT_MODE == 0) {
                *reinterpret_cast<float2*>(Cf + r0 * (long)ldc + col) = make_float2(v00, v01);
                *reinterpret_cast<float2*>(Cf + (r0 + 8) * (long)ldc + col) = make_float2(v10, v11);
            } else {
                uint32_t h0, lo0, h1, lo1;
                split2(v00, v01, h0, lo0);
                split2(v10, v11, h1, lo1);
                *reinterpret_cast<uint32_t*>(Chi + r0 * (long)ldc + col) = h0;
                *reinterpret_cast<uint32_t*>(Clo + r0 * (long)ldc + col) = lo0;
                *reinterpret_cast<uint32_t*>(Chi + (r0 + 8) * (long)ldc + col) = h1;
                *reinterpret_cast<uint32_t*>(Clo + (r0 + 8) * (long)ldc + col) = lo1;
            }
        }
    }
}

// ---------------------------------------------------------------------------
// Logits GEMM: single-term fp16. D = A @ B^T + bias, fp32 accumulate.
// Error: fp16 rounding of both operands, ~4e-4 RMS rel (measured analog 2.9e-4).
// ---------------------------------------------------------------------------
__global__ void __launch_bounds__(256, 1) gemm_f16(
    const __half* __restrict__ A, int lda,
    const __half* __restrict__ B, int ldb,
    const float* __restrict__ bias,
    float* __restrict__ Cf, int ldc, int K)
{
    extern __shared__ char smem[];
    const uint32_t sb = cvta_smem(smem);
    const int tid = threadIdx.x;
    const int w   = tid >> 5;
    const int l   = tid & 31;
    const int wm  = (w >> 2) * 64;
    const int wn  = (w & 3) * 32;
    const long m0 = (long)blockIdx.y * BM;
    const long n0 = (long)blockIdx.x * BN;

    const int lrow  = ((l >> 3) & 1) * 8 + (l & 7);
    const int lkseg = ((l >> 4) & 1) * 16;

    const int NC = K >> 6;

    const int ldr  = tid >> 3;
    const int ldc8 = (tid & 7) * 8;

    auto load_part = [&](int c, uint32_t sbase, int it) {
        const int k0 = c << 6;
        const int r = it * 32 + ldr;
        const uint32_t so = swz((uint32_t)(r * 128) + (uint32_t)((tid & 7) * 16));
        const long ga = (m0 + r) * (long)lda + k0 + ldc8;
        const long gb = (n0 + r) * (long)ldb + k0 + ldc8;
        cp16(sbase + so,          A + ga);
        cp16(sbase + L_TILE + so, B + gb);
    };
    auto load_chunk = [&](int c, int stage) {
        const uint32_t sbase = sb + (uint32_t)stage * L_STAGE;
        #pragma unroll
        for (int it = 0; it < 4; ++it) load_part(c, sbase, it);
    };

    float acc[4][4][4];
    #pragma unroll
    for (int i = 0; i < 4; ++i)
        #pragma unroll
        for (int j = 0; j < 4; ++j)
            #pragma unroll
            for (int q = 0; q < 4; ++q) acc[i][j][q] = 0.0f;

    uint32_t Af[2][4][4], Bf[2][2][4];

    auto ld_frag = [&](int buf, uint32_t sbase, int ks) {
        const int kb = ks * 32 + lkseg;
        #pragma unroll
        for (int mf = 0; mf < 4; ++mf) {
            const uint32_t off = swz((uint32_t)((wm + mf * 16 + lrow) * 128 + kb));
            ldsm4(Af[buf][mf], sbase + off);
        }
        #pragma unroll
        for (int nf2 = 0; nf2 < 2; ++nf2) {
            const uint32_t off = swz((uint32_t)((wn + nf2 * 16 + lrow) * 128 + kb));
            ldsm4(Bf[buf][nf2], sbase + L_TILE + off);
        }
    };
    auto mma_all = [&](int buf) {
        #pragma unroll
        for (int mf = 0; mf < 4; ++mf)
            #pragma unroll
            for (int nf = 0; nf < 4; ++nf) {
                const int p = nf >> 1, q = nf & 1;
                mma16816h(acc[mf][nf], Af[buf][mf], Bf[buf][p][q], Bf[buf][p][q + 2]);
            }
    };

    load_chunk(0, 0); cp_commit();
    load_chunk(1, 1); cp_commit();

    for (int c = 0; c < NC; ++c) {
        if (c + 1 < NC) asm volatile("cp.async.wait_group 1;" ::: "memory");
        else            asm volatile("cp.async.wait_group 0;" ::: "memory");
        __syncthreads();

        const uint32_t sbase = sb + (uint32_t)(c % STAGES) * L_STAGE;
        const int cn = c + 2;
        const uint32_t nbase = sb + (uint32_t)(cn % STAGES) * L_STAGE;
        const bool has_next = cn < NC;

        ld_frag(0, sbase, 0);
        #pragma unroll
        for (int ks = 0; ks < 4; ++ks) {
            if (ks < 3) ld_frag((ks + 1) & 1, sbase, ks + 1);
            if (has_next) load_part(cn, nbase, ks);
            mma_all(ks & 1);
        }
        if (has_next) cp_commit();
    }

    const int tig = l & 3, grp = l >> 2;
    #pragma unroll
    for (int nf = 0; nf < 4; ++nf) {
        const long col = n0 + wn + nf * 8 + 2 * tig;
        const float b0 = bias[col], b1 = bias[col + 1];
        #pragma unroll
        for (int mf = 0; mf < 4; ++mf) {
            const long r0 = m0 + wm + mf * 16 + grp;
            *reinterpret_cast<float2*>(Cf + r0 * (long)ldc + col) =
                make_float2(acc[mf][nf][0] + b0, acc[mf][nf][1] + b1);
            *reinterpret_cast<float2*>(Cf + (r0 + 8) * (long)ldc + col) =
                make_float2(acc[mf][nf][2] + b0, acc[mf][nf][3] + b1);
        }
    }
}

// ---------------------------------------------------------------------------
// Launch
// ---------------------------------------------------------------------------
extern "C" void kernel_launch(void* const* d_in, const int* in_sizes, int n_in,
                              void* d_out, int out_size)
{
    const int*   ids   = (const int*)  d_in[0];
    const float* table = (const float*)d_in[1];
    const float* en_g  = (const float*)d_in[2];
    const float* en_b  = (const float*)d_in[3];
    const float* Wb    = (const float*)d_in[4];
    const float* bb    = (const float*)d_in[5];
    const float* cn_g  = (const float*)d_in[6];
    const float* cn_b  = (const float*)d_in[7];
    const float* tn_g  = (const float*)d_in[8];
    const float* tn_b  = (const float*)d_in[9];
    const float* out_W = (const float*)d_in[10];
    const float* out_b = (const float*)d_in[11];
    float* logits = (float*)d_out;

    __nv_bfloat16 *xhi, *xlo, *yhi, *ylo, *whi, *wlo;
    __half *th, *owh;
    float *h2;
    cudaGetSymbolAddress((void**)&xhi,  g_xhi);
    cudaGetSymbolAddress((void**)&xlo,  g_xlo);
    cudaGetSymbolAddress((void**)&yhi,  g_yhi);
    cudaGetSymbolAddress((void**)&ylo,  g_ylo);
    cudaGetSymbolAddress((void**)&whi,  g_whi);
    cudaGetSymbolAddress((void**)&wlo,  g_wlo);
    cudaGetSymbolAddress((void**)&th,   g_th);
    cudaGetSymbolAddress((void**)&owh,  g_owh);
    cudaGetSymbolAddress((void**)&h2,   g_h2);

    cudaFuncSetAttribute(gemm_mma<true, 1>,  cudaFuncAttributeMaxDynamicSharedMemorySize, SMEM_SZ);
    cudaFuncSetAttribute(gemm_mma<true, 0>,  cudaFuncAttributeMaxDynamicSharedMemorySize, SMEM_SZ);
    cudaFuncSetAttribute(gemm_f16,           cudaFuncAttributeMaxDynamicSharedMemorySize, L_SMEM);

    // 1) split FNN weights bf16 hi/lo; out_W -> fp16
    f32_to_bf16pair<<<W_ELEMS / 4 / 256, 256>>>(
        (const float4*)Wb, (uint2*)whi, (uint2*)wlo, W_ELEMS / 4);
    f32_to_f16<<<OW_ELEMS / 4 / 256, 256>>>(
        (const float4*)out_W, (uint2*)owh, OW_ELEMS / 4);

    // 2) embedding + LN
    embed_ln_kernel<<<NTOK, 128>>>(ids, table, en_g, en_b);

    // 3) three residual blocks (bf16x3 FNN)
    const dim3 fnn_grid(H / BN, NTOK / BM);           // (8, 32)
    for (int bi = 0; bi < 3; ++bi) {
        const __nv_bfloat16* W0h = whi + (long)(bi * 2 + 0) * H * H;
        const __nv_bfloat16* W0l = wlo + (long)(bi * 2 + 0) * H * H;
        const __nv_bfloat16* W1h = whi + (long)(bi * 2 + 1) * H * H;
        const __nv_bfloat16* W1l = wlo + (long)(bi * 2 + 1) * H * H;
        const float* b0 = bb + (bi * 2 + 0) * H;
        const float* b1 = bb + (bi * 2 + 1) * H;

        gemm_mma<true, 1><<<fnn_grid, 256, SMEM_SZ>>>(
            xhi, xlo, H, W0h, W0l, H, b0,
            (float*)nullptr, yhi, ylo, H, H);
        gemm_mma<true, 0><<<fnn_grid, 256, SMEM_SZ>>>(
            yhi, ylo, H, W1h, W1l, H, b1,
            h2, (__nv_bfloat16*)nullptr, (__nv_bfloat16*)nullptr, H, H);
        resid_ln_kernel<<<dim3(NTOK, 2), 128>>>(cn_g + bi * C, cn_b + bi * C,
                                                tn_g + bi * E, tn_b + bi * E);
    }

    // 4) tok -> fp16, then logits = tok @ out_W^T + out_b (fp16 single-term)
    tok_to_f16<<<NTOK, 128>>>();
    const dim3 out_grid(V / BN, NTOK / BM);           // (250, 32)
    gemm_f16<<<out_grid, 256, L_SMEM>>>(
        th, E, owh, C, out_b, logits, V, C);
}

// round 9
// speedup vs baseline: 1.9491x; 1.1612x over previous
#include <cuda_runtime.h>
#include <cuda_fp16.h>
#include <cstdint>

// Problem constants (fixed by the dataset)
constexpr int NTOK = 4096;      // B*S = 4*1024
constexpr int E    = 512;
constexpr int C    = 512;
constexpr int H    = 1024;
constexpr int V    = 32000;
constexpr float EPS = 1e-5f;

constexpr int W_ELEMS  = 3 * 2 * H * H;
constexpr int OW_ELEMS = V * C;

// Tiling: 128x128x64, 256 threads, warp 64x32
constexpr int BM = 128, BN = 128, BK = 64;
constexpr int TILE16  = BM * BK * 2;              // 16384 bytes per fp16 tile
constexpr int STAGES  = 3;
// FNN stage: Ah|Al|B = 3 tiles
constexpr int F_STAGE = 3 * TILE16;               // 49152
constexpr int F_SMEM  = STAGES * F_STAGE;         // 147456
// Logits stage: A|B = 2 tiles
constexpr int L_STAGE = 2 * TILE16;               // 32768
constexpr int L_SMEM  = STAGES * L_STAGE;         // 98304

// Scratch (allocation-free rule: __device__ globals)
__device__ float g_hbuf[NTOK * H];                // fp32 residual state [ctx|tok]
__device__ float g_h2[NTOK * H];                  // fp32 FNN block output
__device__ __half g_xh[NTOK * H], g_xl[NTOK * H]; // x fp16 hi/lo (GEMM-1 in; xh[:,C:] = logits A)
__device__ __half g_yh[NTOK * H], g_yl[NTOK * H]; // GEMM-2 input fp16 hi/lo
__device__ __half g_wh[W_ELEMS];                  // FNN weights fp16
__device__ __half g_owh[OW_ELEMS];                // out_W fp16

// ---------------------------------------------------------------------------
// PTX helpers
// ---------------------------------------------------------------------------
__device__ __forceinline__ uint32_t cvta_smem(const void* p) {
    uint32_t a;
    asm("{\n\t.reg .u64 t;\n\tcvta.to.shared.u64 t, %1;\n\tcvt.u32.u64 %0, t;\n\t}"
        : "=r"(a) : "l"(p));
    return a;
}
__device__ __forceinline__ uint32_t swz(uint32_t o) { return o ^ ((o >> 3) & 0x70); }

__device__ __forceinline__ void cp16(uint32_t dst, const void* src) {
    asm volatile("cp.async.cg.shared.global [%0], [%1], 16;" :: "r"(dst), "l"(src));
}
__device__ __forceinline__ void cp_commit() {
    asm volatile("cp.async.commit_group;" ::: "memory");
}

__device__ __forceinline__ void ldsm4(uint32_t* r, uint32_t addr) {
    asm volatile("ldmatrix.sync.aligned.m8n8.x4.shared.b16 {%0,%1,%2,%3}, [%4];"
                 : "=r"(r[0]), "=r"(r[1]), "=r"(r[2]), "=r"(r[3]) : "r"(addr));
}

__device__ __forceinline__ void mma16816h(float* d, const uint32_t* a,
                                          uint32_t b0, uint32_t b1) {
    asm("mma.sync.aligned.m16n8k16.row.col.f32.f16.f16.f32 "
        "{%0,%1,%2,%3}, {%4,%5,%6,%7}, {%8,%9}, {%0,%1,%2,%3};"
        : "+f"(d[0]), "+f"(d[1]), "+f"(d[2]), "+f"(d[3])
        : "r"(a[0]), "r"(a[1]), "r"(a[2]), "r"(a[3]), "r"(b0), "r"(b1));
}

__device__ __forceinline__ void split2h(float a, float b, uint32_t& hi, uint32_t& lo) {
    __half ha = __float2half_rn(a), hb = __float2half_rn(b);
    __half la = __float2half_rn(a - __half2float(ha));
    __half lb = __float2half_rn(b - __half2float(hb));
    hi = (uint32_t)__half_as_ushort(ha) | ((uint32_t)__half_as_ushort(hb) << 16);
    lo = (uint32_t)__half_as_ushort(la) | ((uint32_t)__half_as_ushort(lb) << 16);
}

// ---------------------------------------------------------------------------
// fp32 -> fp16 (weights)
// ---------------------------------------------------------------------------
__global__ void __launch_bounds__(256) f32_to_f16(
    const float4* __restrict__ src, uint2* __restrict__ dst, int n4)
{
    const int i = blockIdx.x * 256 + threadIdx.x;
    if (i >= n4) return;
    const float4 x = src[i];
    uint32_t a = (uint32_t)__half_as_ushort(__float2half_rn(x.x)) |
                 ((uint32_t)__half_as_ushort(__float2half_rn(x.y)) << 16);
    uint32_t b = (uint32_t)__half_as_ushort(__float2half_rn(x.z)) |
                 ((uint32_t)__half_as_ushort(__float2half_rn(x.w)) << 16);
    dst[i] = make_uint2(a, b);
}

// ---------------------------------------------------------------------------
// LN reduction helper (128 threads = 4 warps)
// ---------------------------------------------------------------------------
__device__ __forceinline__ void block_reduce_2(float& s, float& s2) {
    #pragma unroll
    for (int o = 16; o > 0; o >>= 1) {
        s  += __shfl_xor_sync(0xFFFFFFFFu, s,  o);
        s2 += __shfl_xor_sync(0xFFFFFFFFu, s2, o);
    }
    __shared__ float red[8];
    int wid = threadIdx.x >> 5;
    int lid = threadIdx.x & 31;
    if (lid == 0) { red[wid] = s; red[4 + wid] = s2; }
    __syncthreads();
    s  = red[0] + red[1] + red[2] + red[3];
    s2 = red[4] + red[5] + red[6] + red[7];
}

// ---------------------------------------------------------------------------
// Embedding gather + LN -> hbuf fp32 [0|tok] and x fp16 hi/lo (full row)
// ---------------------------------------------------------------------------
__global__ void __launch_bounds__(128) embed_ln_kernel(
    const int* __restrict__ ids, const float* __restrict__ table,
    const float* __restrict__ g, const float* __restrict__ b)
{
    const int tok = blockIdx.x;
    const int tid = threadIdx.x;
    const long id = ids[tok];

    float4 x = reinterpret_cast<const float4*>(table + id * (long)E)[tid];
    float s  = x.x + x.y + x.z + x.w;
    float s2 = x.x * x.x + x.y * x.y + x.z * x.z + x.w * x.w;
    block_reduce_2(s, s2);

    const float mean = s * (1.0f / E);
    const float var  = s2 * (1.0f / E) - mean * mean;
    const float rstd = rsqrtf(var + EPS);

    float4 gg = reinterpret_cast<const float4*>(g)[tid];
    float4 bb = reinterpret_cast<const float4*>(b)[tid];
    float4 y;
    y.x = (x.x - mean) * rstd * gg.x + bb.x;
    y.y = (x.y - mean) * rstd * gg.y + bb.y;
    y.z = (x.z - mean) * rstd * gg.z + bb.z;
    y.w = (x.w - mean) * rstd * gg.w + bb.w;

    const long rbase = (long)tok * H;
    float* row = g_hbuf + rbase;
    reinterpret_cast<float4*>(row + C)[tid] = y;
    reinterpret_cast<float4*>(row)[tid] = make_float4(0.f, 0.f, 0.f, 0.f);

    uint32_t h0, l0, h1, l1;
    split2h(y.x, y.y, h0, l0);
    split2h(y.z, y.w, h1, l1);
    reinterpret_cast<uint2*>(g_xh + rbase + C)[tid] = make_uint2(h0, h1);
    reinterpret_cast<uint2*>(g_xl + rbase + C)[tid] = make_uint2(l0, l1);
    reinterpret_cast<uint2*>(g_xh + rbase)[tid] = make_uint2(0, 0);
    reinterpret_cast<uint2*>(g_xl + rbase)[tid] = make_uint2(0, 0);
}

// ---------------------------------------------------------------------------
// Residual + LN; writes hbuf fp32 and x fp16 hi/lo
// ---------------------------------------------------------------------------
__global__ void __launch_bounds__(128) resid_ln_kernel(
    const float* __restrict__ cg, const float* __restrict__ cb,
    const float* __restrict__ tg, const float* __restrict__ tb)
{
    const int tok  = blockIdx.x;
    const int half = blockIdx.y;
    const int tid  = threadIdx.x;
    const float* g  = half ? tg : cg;
    const float* bp = half ? tb : cb;

    const long base = (long)tok * H + half * C;
    float4 a = reinterpret_cast<const float4*>(g_hbuf + base)[tid];
    float4 h = reinterpret_cast<const float4*>(g_h2 + base)[tid];
    float4 x;
    x.x = a.x + h.x; x.y = a.y + h.y; x.z = a.z + h.z; x.w = a.w + h.w;

    float s  = x.x + x.y + x.z + x.w;
    float s2 = x.x * x.x + x.y * x.y + x.z * x.z + x.w * x.w;
    block_reduce_2(s, s2);

    const float mean = s * (1.0f / C);
    const float var  = s2 * (1.0f / C) - mean * mean;
    const float rstd = rsqrtf(var + EPS);

    float4 gg = reinterpret_cast<const float4*>(g)[tid];
    float4 bb = reinterpret_cast<const float4*>(bp)[tid];
    float4 y;
    y.x = (x.x - mean) * rstd * gg.x + bb.x;
    y.y = (x.y - mean) * rstd * gg.y + bb.y;
    y.z = (x.z - mean) * rstd * gg.z + bb.z;
    y.w = (x.w - mean) * rstd * gg.w + bb.w;
    reinterpret_cast<float4*>(g_hbuf + base)[tid] = y;

    uint32_t h0, l0, h1, l1;
    split2h(y.x, y.y, h0, l0);
    split2h(y.z, y.w, h1, l1);
    reinterpret_cast<uint2*>(g_xh + base)[tid] = make_uint2(h0, h1);
    reinterpret_cast<uint2*>(g_xl + base)[tid] = make_uint2(l0, l1);
}

// ---------------------------------------------------------------------------
// FNN GEMM: fp16 2-term. D = (Ah + Al) @ B^T + bias, fp32 accumulate.
// A = activations split fp16 hi/lo (exact to ~22 bits), B = weights fp16.
// Error per GEMM ~2.1e-4 (R7-measured structure).
// OUT_MODE 0: fp32 out. OUT_MODE 1: fp16 hi/lo out (next GEMM input).
// ---------------------------------------------------------------------------
template <bool RELU, int OUT_MODE>
__global__ void __launch_bounds__(256, 1) gemm_f16_2t(
    const __half* __restrict__ Ahi, const __half* __restrict__ Alo, int lda,
    const __half* __restrict__ B, int ldb,
    const float* __restrict__ bias,
    float* __restrict__ Cf,
    __half* __restrict__ Chi, __half* __restrict__ Clo,
    int ldc, int K)
{
    extern __shared__ char smem[];
    const uint32_t sb = cvta_smem(smem);
    const int tid = threadIdx.x;
    const int w   = tid >> 5;
    const int l   = tid & 31;
    const int wm  = (w >> 2) * 64;
    const int wn  = (w & 3) * 32;
    const long m0 = (long)blockIdx.y * BM;
    const long n0 = (long)blockIdx.x * BN;

    const int lrow  = ((l >> 3) & 1) * 8 + (l & 7);
    const int lkseg = ((l >> 4) & 1) * 16;

    const int NC = K >> 6;

    const int ldr  = tid >> 3;
    const int ldc8 = (tid & 7) * 8;

    auto load_part = [&](int c, uint32_t sbase, int it) {
        const int k0 = c << 6;
        const int r = it * 32 + ldr;
        const uint32_t so = swz((uint32_t)(r * 128) + (uint32_t)((tid & 7) * 16));
        const long ga = (m0 + r) * (long)lda + k0 + ldc8;
        const long gb = (n0 + r) * (long)ldb + k0 + ldc8;
        cp16(sbase + so,              Ahi + ga);
        cp16(sbase + TILE16 + so,     Alo + ga);
        cp16(sbase + 2 * TILE16 + so, B + gb);
    };
    auto load_chunk = [&](int c, int stage) {
        const uint32_t sbase = sb + (uint32_t)stage * F_STAGE;
        #pragma unroll
        for (int it = 0; it < 4; ++it) load_part(c, sbase, it);
    };

    float acc[4][4][4];
    #pragma unroll
    for (int i = 0; i < 4; ++i)
        #pragma unroll
        for (int j = 0; j < 4; ++j)
            #pragma unroll
            for (int q = 0; q < 4; ++q) acc[i][j][q] = 0.0f;

    uint32_t Ah[2][4][4], Al[2][4][4], Bf[2][2][4];

    auto ld_frag = [&](int buf, uint32_t sbase, int ks) {
        const int kb = ks * 32 + lkseg;
        #pragma unroll
        for (int mf = 0; mf < 4; ++mf) {
            const uint32_t off = swz((uint32_t)((wm + mf * 16 + lrow) * 128 + kb));
            ldsm4(Ah[buf][mf], sbase + off);
            ldsm4(Al[buf][mf], sbase + TILE16 + off);
        }
        #pragma unroll
        for (int nf2 = 0; nf2 < 2; ++nf2) {
            const uint32_t off = swz((uint32_t)((wn + nf2 * 16 + lrow) * 128 + kb));
            ldsm4(Bf[buf][nf2], sbase + 2 * TILE16 + off);
        }
    };
    auto mma_all = [&](int buf) {
        #pragma unroll
        for (int mf = 0; mf < 4; ++mf)
            #pragma unroll
            for (int nf = 0; nf < 4; ++nf) {
                const int p = nf >> 1, q = nf & 1;
                mma16816h(acc[mf][nf], Ah[buf][mf], Bf[buf][p][q], Bf[buf][p][q + 2]);
            }
        #pragma unroll
        for (int mf = 0; mf < 4; ++mf)
            #pragma unroll
            for (int nf = 0; nf < 4; ++nf) {
                const int p = nf >> 1, q = nf & 1;
                mma16816h(acc[mf][nf], Al[buf][mf], Bf[buf][p][q], Bf[buf][p][q + 2]);
            }
    };

    load_chunk(0, 0); cp_commit();
    if (NC > 1) { load_chunk(1, 1); cp_commit(); }

    for (int c = 0; c < NC; ++c) {
        if (c + 1 < NC) asm volatile("cp.async.wait_group 1;" ::: "memory");
        else            asm volatile("cp.async.wait_group 0;" ::: "memory");
        __syncthreads();

        const uint32_t sbase = sb + (uint32_t)(c % STAGES) * F_STAGE;
        const int cn = c + 2;
        const uint32_t nbase = sb + (uint32_t)(cn % STAGES) * F_STAGE;
        const bool has_next = cn < NC;

        ld_frag(0, sbase, 0);
        #pragma unroll
        for (int ks = 0; ks < 4; ++ks) {
            if (ks < 3) ld_frag((ks + 1) & 1, sbase, ks + 1);
            if (has_next) load_part(cn, nbase, ks);
            mma_all(ks & 1);
        }
        if (has_next) cp_commit();
    }

    const int tig = l & 3, grp = l >> 2;
    #pragma unroll
    for (int nf = 0; nf < 4; ++nf) {
        const long col = n0 + wn + nf * 8 + 2 * tig;
        const float b0 = bias[col], b1 = bias[col + 1];
        #pragma unroll
        for (int mf = 0; mf < 4; ++mf) {
            const long r0 = m0 + wm + mf * 16 + grp;
            float v00 = acc[mf][nf][0] + b0, v01 = acc[mf][nf][1] + b1;
            float v10 = acc[mf][nf][2] + b0, v11 = acc[mf][nf][3] + b1;
            if (RELU) {
                v00 = fmaxf(v00, 0.f); v01 = fmaxf(v01, 0.f);
                v10 = fmaxf(v10, 0.f); v11 = fmaxf(v11, 0.f);
            }
            if (OUT_MODE == 0) {
                *reinterpret_cast<float2*>(Cf + r0 * (long)ldc + col) = make_float2(v00, v01);
                *reinterpret_cast<float2*>(Cf + (r0 + 8) * (long)ldc + col) = make_float2(v10, v11);
            } else {
                uint32_t h0, lo0, h1, lo1;
                split2h(v00, v01, h0, lo0);
                split2h(v10, v11, h1, lo1);
                *reinterpret_cast<uint32_t*>(Chi + r0 * (long)ldc + col) = h0;
                *reinterpret_cast<uint32_t*>(Clo + r0 * (long)ldc + col) = lo0;
                *reinterpret_cast<uint32_t*>(Chi + (r0 + 8) * (long)ldc + col) = h1;
                *reinterpret_cast<uint32_t*>(Clo + (r0 + 8) * (long)ldc + col) = lo1;
            }
        }
    }
}

// ---------------------------------------------------------------------------
// Logits GEMM: single-term fp16 (unchanged from R8).
// ---------------------------------------------------------------------------
__global__ void __launch_bounds__(256, 1) gemm_f16(
    const __half* __restrict__ A, int lda,
    const __half* __restrict__ B, int ldb,
    const float* __restrict__ bias,
    float* __restrict__ Cf, int ldc, int K)
{
    extern __shared__ char smem[];
    const uint32_t sb = cvta_smem(smem);
    const int tid = threadIdx.x;
    const int w   = tid >> 5;
    const int l   = tid & 31;
    const int wm  = (w >> 2) * 64;
    const int wn  = (w & 3) * 32;
    const long m0 = (long)blockIdx.y * BM;
    const long n0 = (long)blockIdx.x * BN;

    const int lrow  = ((l >> 3) & 1) * 8 + (l & 7);
    const int lkseg = ((l >> 4) & 1) * 16;

    const int NC = K >> 6;

    const int ldr  = tid >> 3;
    const int ldc8 = (tid & 7) * 8;

    auto load_part = [&](int c, uint32_t sbase, int it) {
        const int k0 = c << 6;
        const int r = it * 32 + ldr;
        const uint32_t so = swz((uint32_t)(r * 128) + (uint32_t)((tid & 7) * 16));
        const long ga = (m0 + r) * (long)lda + k0 + ldc8;
        const long gb = (n0 + r) * (long)ldb + k0 + ldc8;
        cp16(sbase + so,          A + ga);
        cp16(sbase + TILE16 + so, B + gb);
    };
    auto load_chunk = [&](int c, int stage) {
        const uint32_t sbase = sb + (uint32_t)stage * L_STAGE;
        #pragma unroll
        for (int it = 0; it < 4; ++it) load_part(c, sbase, it);
    };

    float acc[4][4][4];
    #pragma unroll
    for (int i = 0; i < 4; ++i)
        #pragma unroll
        for (int j = 0; j < 4; ++j)
            #pragma unroll
            for (int q = 0; q < 4; ++q) acc[i][j][q] = 0.0f;

    uint32_t Af[2][4][4], Bf[2][2][4];

    auto ld_frag = [&](int buf, uint32_t sbase, int ks) {
        const int kb = ks * 32 + lkseg;
        #pragma unroll
        for (int mf = 0; mf < 4; ++mf) {
            const uint32_t off = swz((uint32_t)((wm + mf * 16 + lrow) * 128 + kb));
            ldsm4(Af[buf][mf], sbase + off);
        }
        #pragma unroll
        for (int nf2 = 0; nf2 < 2; ++nf2) {
            const uint32_t off = swz((uint32_t)((wn + nf2 * 16 + lrow) * 128 + kb));
            ldsm4(Bf[buf][nf2], sbase + TILE16 + off);
        }
    };
    auto mma_all = [&](int buf) {
        #pragma unroll
        for (int mf = 0; mf < 4; ++mf)
            #pragma unroll
            for (int nf = 0; nf < 4; ++nf) {
                const int p = nf >> 1, q = nf & 1;
                mma16816h(acc[mf][nf], Af[buf][mf], Bf[buf][p][q], Bf[buf][p][q + 2]);
            }
    };

    load_chunk(0, 0); cp_commit();
    load_chunk(1, 1); cp_commit();

    for (int c = 0; c < NC; ++c) {
        if (c + 1 < NC) asm volatile("cp.async.wait_group 1;" ::: "memory");
        else            asm volatile("cp.async.wait_group 0;" ::: "memory");
        __syncthreads();

        const uint32_t sbase = sb + (uint32_t)(c % STAGES) * L_STAGE;
        const int cn = c + 2;
        const uint32_t nbase = sb + (uint32_t)(cn % STAGES) * L_STAGE;
        const bool has_next = cn < NC;

        ld_frag(0, sbase, 0);
        #pragma unroll
        for (int ks = 0; ks < 4; ++ks) {
            if (ks < 3) ld_frag((ks + 1) & 1, sbase, ks + 1);
            if (has_next) load_part(cn, nbase, ks);
            mma_all(ks & 1);
        }
        if (has_next) cp_commit();
    }

    const int tig = l & 3, grp = l >> 2;
    #pragma unroll
    for (int nf = 0; nf < 4; ++nf) {
        const long col = n0 + wn + nf * 8 + 2 * tig;
        const float b0 = bias[col], b1 = bias[col + 1];
        #pragma unroll
        for (int mf = 0; mf < 4; ++mf) {
            const long r0 = m0 + wm + mf * 16 + grp;
            *reinterpret_cast<float2*>(Cf + r0 * (long)ldc + col) =
                make_float2(acc[mf][nf][0] + b0, acc[mf][nf][1] + b1);
            *reinterpret_cast<float2*>(Cf + (r0 + 8) * (long)ldc + col) =
                make_float2(acc[mf][nf][2] + b0, acc[mf][nf][3] + b1);
        }
    }
}

// ---------------------------------------------------------------------------
// Launch
// ---------------------------------------------------------------------------
extern "C" void kernel_launch(void* const* d_in, const int* in_sizes, int n_in,
                              void* d_out, int out_size)
{
    const int*   ids   = (const int*)  d_in[0];
    const float* table = (const float*)d_in[1];
    const float* en_g  = (const float*)d_in[2];
    const float* en_b  = (const float*)d_in[3];
    const float* Wb    = (const float*)d_in[4];
    const float* bb    = (const float*)d_in[5];
    const float* cn_g  = (const float*)d_in[6];
    const float* cn_b  = (const float*)d_in[7];
    const float* tn_g  = (const float*)d_in[8];
    const float* tn_b  = (const float*)d_in[9];
    const float* out_W = (const float*)d_in[10];
    const float* out_b = (const float*)d_in[11];
    float* logits = (float*)d_out;

    __half *xh, *xl, *yh, *yl, *wh, *owh;
    float *h2;
    cudaGetSymbolAddress((void**)&xh,  g_xh);
    cudaGetSymbolAddress((void**)&xl,  g_xl);
    cudaGetSymbolAddress((void**)&yh,  g_yh);
    cudaGetSymbolAddress((void**)&yl,  g_yl);
    cudaGetSymbolAddress((void**)&wh,  g_wh);
    cudaGetSymbolAddress((void**)&owh, g_owh);
    cudaGetSymbolAddress((void**)&h2,  g_h2);

    cudaFuncSetAttribute(gemm_f16_2t<true, 1>, cudaFuncAttributeMaxDynamicSharedMemorySize, F_SMEM);
    cudaFuncSetAttribute(gemm_f16_2t<true, 0>, cudaFuncAttributeMaxDynamicSharedMemorySize, F_SMEM);
    cudaFuncSetAttribute(gemm_f16,             cudaFuncAttributeMaxDynamicSharedMemorySize, L_SMEM);

    // 1) weights -> fp16
    f32_to_f16<<<W_ELEMS / 4 / 256, 256>>>(
        (const float4*)Wb, (uint2*)wh, W_ELEMS / 4);
    f32_to_f16<<<OW_ELEMS / 4 / 256, 256>>>(
        (const float4*)out_W, (uint2*)owh, OW_ELEMS / 4);

    // 2) embedding + LN
    embed_ln_kernel<<<NTOK, 128>>>(ids, table, en_g, en_b);

    // 3) three residual blocks (fp16 2-term FNN)
    const dim3 fnn_grid(H / BN, NTOK / BM);           // (8, 32)
    for (int bi = 0; bi < 3; ++bi) {
        const __half* W0 = wh + (long)(bi * 2 + 0) * H * H;
        const __half* W1 = wh + (long)(bi * 2 + 1) * H * H;
        const float* b0 = bb + (bi * 2 + 0) * H;
        const float* b1 = bb + (bi * 2 + 1) * H;

        gemm_f16_2t<true, 1><<<fnn_grid, 256, F_SMEM>>>(
            xh, xl, H, W0, H, b0,
            (float*)nullptr, yh, yl, H, H);
        gemm_f16_2t<true, 0><<<fnn_grid, 256, F_SMEM>>>(
            yh, yl, H, W1, H, b1,
            h2, (__half*)nullptr, (__half*)nullptr, H, H);
        resid_ln_kernel<<<dim3(NTOK, 2), 128>>>(cn_g + bi * C, cn_b + bi * C,
                                                tn_g + bi * E, tn_b + bi * E);
    }

    // 4) logits = tok @ out_W^T + out_b  (A = xh[:, C:] fp16, single term)
    const dim3 out_grid(V / BN, NTOK / BM);           // (250, 32)
    gemm_f16<<<out_grid, 256, L_SMEM>>>(
        xh + C, H, owh, C, out_b, logits, V, C);
}

// round 10
// speedup vs baseline: 2.3837x; 1.2230x over previous
#include <cuda_runtime.h>
#include <cuda_fp16.h>
#include <cstdint>

// Problem constants (fixed by the dataset)
constexpr int NTOK = 4096;      // B*S = 4*1024
constexpr int E    = 512;
constexpr int C    = 512;
constexpr int H    = 1024;
constexpr int V    = 32000;
constexpr float EPS = 1e-5f;

constexpr int W_ELEMS  = 3 * 2 * H * H;
constexpr int OW_ELEMS = V * C;

// Tiling: 128x128x64, 256 threads, warp 64x32. Stage = A|B fp16 tiles.
constexpr int BM = 128, BN = 128, BK = 64;
constexpr int TILE16  = BM * BK * 2;              // 16384 bytes per fp16 tile
constexpr int STAGES  = 3;
constexpr int G_STAGE = 2 * TILE16;               // 32768
constexpr int G_SMEM  = STAGES * G_STAGE;         // 98304

// Scratch (allocation-free rule: __device__ globals)
__device__ float g_hbuf[NTOK * H];                // fp32 residual state [ctx|tok]
__device__ float g_h2[NTOK * H];                  // fp32 FNN block output
__device__ __half g_xh[NTOK * H];                 // x fp16 (GEMM-1 in; xh[:,C:] = logits A)
__device__ __half g_yh[NTOK * H];                 // GEMM-2 input fp16
__device__ __half g_wh[W_ELEMS];                  // FNN weights fp16
__device__ __half g_owh[OW_ELEMS];                // out_W fp16

// ---------------------------------------------------------------------------
// PTX helpers
// ---------------------------------------------------------------------------
__device__ __forceinline__ uint32_t cvta_smem(const void* p) {
    uint32_t a;
    asm("{\n\t.reg .u64 t;\n\tcvta.to.shared.u64 t, %1;\n\tcvt.u32.u64 %0, t;\n\t}"
        : "=r"(a) : "l"(p));
    return a;
}
__device__ __forceinline__ uint32_t swz(uint32_t o) { return o ^ ((o >> 3) & 0x70); }

__device__ __forceinline__ void cp16(uint32_t dst, const void* src) {
    asm volatile("cp.async.cg.shared.global [%0], [%1], 16;" :: "r"(dst), "l"(src));
}
__device__ __forceinline__ void cp_commit() {
    asm volatile("cp.async.commit_group;" ::: "memory");
}

__device__ __forceinline__ void ldsm4(uint32_t* r, uint32_t addr) {
    asm volatile("ldmatrix.sync.aligned.m8n8.x4.shared.b16 {%0,%1,%2,%3}, [%4];"
                 : "=r"(r[0]), "=r"(r[1]), "=r"(r[2]), "=r"(r[3]) : "r"(addr));
}

__device__ __forceinline__ void mma16816h(float* d, const uint32_t* a,
                                          uint32_t b0, uint32_t b1) {
    asm("mma.sync.aligned.m16n8k16.row.col.f32.f16.f16.f32 "
        "{%0,%1,%2,%3}, {%4,%5,%6,%7}, {%8,%9}, {%0,%1,%2,%3};"
        : "+f"(d[0]), "+f"(d[1]), "+f"(d[2]), "+f"(d[3])
        : "r"(a[0]), "r"(a[1]), "r"(a[2]), "r"(a[3]), "r"(b0), "r"(b1));
}

__device__ __forceinline__ uint32_t pack_h2(float a, float b) {
    return (uint32_t)__half_as_ushort(__float2half_rn(a)) |
           ((uint32_t)__half_as_ushort(__float2half_rn(b)) << 16);
}

// ---------------------------------------------------------------------------
// fp32 -> fp16 (weights)
// ---------------------------------------------------------------------------
__global__ void __launch_bounds__(256) f32_to_f16(
    const float4* __restrict__ src, uint2* __restrict__ dst, int n4)
{
    const int i = blockIdx.x * 256 + threadIdx.x;
    if (i >= n4) return;
    const float4 x = src[i];
    dst[i] = make_uint2(pack_h2(x.x, x.y), pack_h2(x.z, x.w));
}

// ---------------------------------------------------------------------------
// LN reduction helper (128 threads = 4 warps)
// ---------------------------------------------------------------------------
__device__ __forceinline__ void block_reduce_2(float& s, float& s2) {
    #pragma unroll
    for (int o = 16; o > 0; o >>= 1) {
        s  += __shfl_xor_sync(0xFFFFFFFFu, s,  o);
        s2 += __shfl_xor_sync(0xFFFFFFFFu, s2, o);
    }
    __shared__ float red[8];
    int wid = threadIdx.x >> 5;
    int lid = threadIdx.x & 31;
    if (lid == 0) { red[wid] = s; red[4 + wid] = s2; }
    __syncthreads();
    s  = red[0] + red[1] + red[2] + red[3];
    s2 = red[4] + red[5] + red[6] + red[7];
}

// ---------------------------------------------------------------------------
// Embedding gather + LN -> hbuf fp32 [0|tok] and x fp16 (full row)
// ---------------------------------------------------------------------------
__global__ void __launch_bounds__(128) embed_ln_kernel(
    const int* __restrict__ ids, const float* __restrict__ table,
    const float* __restrict__ g, const float* __restrict__ b)
{
    const int tok = blockIdx.x;
    const int tid = threadIdx.x;
    const long id = ids[tok];

    float4 x = reinterpret_cast<const float4*>(table + id * (long)E)[tid];
    float s  = x.x + x.y + x.z + x.w;
    float s2 = x.x * x.x + x.y * x.y + x.z * x.z + x.w * x.w;
    block_reduce_2(s, s2);

    const float mean = s * (1.0f / E);
    const float var  = s2 * (1.0f / E) - mean * mean;
    const float rstd = rsqrtf(var + EPS);

    float4 gg = reinterpret_cast<const float4*>(g)[tid];
    float4 bb = reinterpret_cast<const float4*>(b)[tid];
    float4 y;
    y.x = (x.x - mean) * rstd * gg.x + bb.x;
    y.y = (x.y - mean) * rstd * gg.y + bb.y;
    y.z = (x.z - mean) * rstd * gg.z + bb.z;
    y.w = (x.w - mean) * rstd * gg.w + bb.w;

    const long rbase = (long)tok * H;
    float* row = g_hbuf + rbase;
    reinterpret_cast<float4*>(row + C)[tid] = y;
    reinterpret_cast<float4*>(row)[tid] = make_float4(0.f, 0.f, 0.f, 0.f);

    reinterpret_cast<uint2*>(g_xh + rbase + C)[tid] =
        make_uint2(pack_h2(y.x, y.y), pack_h2(y.z, y.w));
    reinterpret_cast<uint2*>(g_xh + rbase)[tid] = make_uint2(0, 0);
}

// ---------------------------------------------------------------------------
// Residual + LN; writes hbuf fp32 and x fp16
// ---------------------------------------------------------------------------
__global__ void __launch_bounds__(128) resid_ln_kernel(
    const float* __restrict__ cg, const float* __restrict__ cb,
    const float* __restrict__ tg, const float* __restrict__ tb)
{
    const int tok  = blockIdx.x;
    const int half = blockIdx.y;
    const int tid  = threadIdx.x;
    const float* g  = half ? tg : cg;
    const float* bp = half ? tb : cb;

    const long base = (long)tok * H + half * C;
    float4 a = reinterpret_cast<const float4*>(g_hbuf + base)[tid];
    float4 h = reinterpret_cast<const float4*>(g_h2 + base)[tid];
    float4 x;
    x.x = a.x + h.x; x.y = a.y + h.y; x.z = a.z + h.z; x.w = a.w + h.w;

    float s  = x.x + x.y + x.z + x.w;
    float s2 = x.x * x.x + x.y * x.y + x.z * x.z + x.w * x.w;
    block_reduce_2(s, s2);

    const float mean = s * (1.0f / C);
    const float var  = s2 * (1.0f / C) - mean * mean;
    const float rstd = rsqrtf(var + EPS);

    float4 gg = reinterpret_cast<const float4*>(g)[tid];
    float4 bb = reinterpret_cast<const float4*>(bp)[tid];
    float4 y;
    y.x = (x.x - mean) * rstd * gg.x + bb.x;
    y.y = (x.y - mean) * rstd * gg.y + bb.y;
    y.z = (x.z - mean) * rstd * gg.z + bb.z;
    y.w = (x.w - mean) * rstd * gg.w + bb.w;
    reinterpret_cast<float4*>(g_hbuf + base)[tid] = y;

    reinterpret_cast<uint2*>(g_xh + base)[tid] =
        make_uint2(pack_h2(y.x, y.y), pack_h2(y.z, y.w));
}

// ---------------------------------------------------------------------------
// Unified single-term fp16 GEMM: D = A @ B^T + bias, fp32 accumulate.
// RELU: apply relu. OUT16: write __half (Ch) instead of fp32 (Cf).
// 3-stage cp.async pipeline, SW128 swizzle, register double-buffered ldmatrix.
// ---------------------------------------------------------------------------
template <bool RELU, bool OUT16>
__global__ void __launch_bounds__(256, 1) gemm_f16(
    const __half* __restrict__ A, int lda,
    const __half* __restrict__ B, int ldb,
    const float* __restrict__ bias,
    float* __restrict__ Cf, __half* __restrict__ Ch,
    int ldc, int K)
{
    extern __shared__ char smem[];
    const uint32_t sb = cvta_smem(smem);
    const int tid = threadIdx.x;
    const int w   = tid >> 5;
    const int l   = tid & 31;
    const int wm  = (w >> 2) * 64;
    const int wn  = (w & 3) * 32;
    const long m0 = (long)blockIdx.y * BM;
    const long n0 = (long)blockIdx.x * BN;

    const int lrow  = ((l >> 3) & 1) * 8 + (l & 7);
    const int lkseg = ((l >> 4) & 1) * 16;

    const int NC = K >> 6;

    const int ldr  = tid >> 3;
    const int ldc8 = (tid & 7) * 8;

    auto load_part = [&](int c, uint32_t sbase, int it) {
        const int k0 = c << 6;
        const int r = it * 32 + ldr;
        const uint32_t so = swz((uint32_t)(r * 128) + (uint32_t)((tid & 7) * 16));
        const long ga = (m0 + r) * (long)lda + k0 + ldc8;
        const long gb = (n0 + r) * (long)ldb + k0 + ldc8;
        cp16(sbase + so,          A + ga);
        cp16(sbase + TILE16 + so, B + gb);
    };
    auto load_chunk = [&](int c, int stage) {
        const uint32_t sbase = sb + (uint32_t)stage * G_STAGE;
        #pragma unroll
        for (int it = 0; it < 4; ++it) load_part(c, sbase, it);
    };

    float acc[4][4][4];
    #pragma unroll
    for (int i = 0; i < 4; ++i)
        #pragma unroll
        for (int j = 0; j < 4; ++j)
            #pragma unroll
            for (int q = 0; q < 4; ++q) acc[i][j][q] = 0.0f;

    uint32_t Af[2][4][4], Bf[2][2][4];

    auto ld_frag = [&](int buf, uint32_t sbase, int ks) {
        const int kb = ks * 32 + lkseg;
        #pragma unroll
        for (int mf = 0; mf < 4; ++mf) {
            const uint32_t off = swz((uint32_t)((wm + mf * 16 + lrow) * 128 + kb));
            ldsm4(Af[buf][mf], sbase + off);
        }
        #pragma unroll
        for (int nf2 = 0; nf2 < 2; ++nf2) {
            const uint32_t off = swz((uint32_t)((wn + nf2 * 16 + lrow) * 128 + kb));
            ldsm4(Bf[buf][nf2], sbase + TILE16 + off);
        }
    };
    auto mma_all = [&](int buf) {
        #pragma unroll
        for (int mf = 0; mf < 4; ++mf)
            #pragma unroll
            for (int nf = 0; nf < 4; ++nf) {
                const int p = nf >> 1, q = nf & 1;
                mma16816h(acc[mf][nf], Af[buf][mf], Bf[buf][p][q], Bf[buf][p][q + 2]);
            }
    };

    load_chunk(0, 0); cp_commit();
    if (NC > 1) { load_chunk(1, 1); cp_commit(); }

    for (int c = 0; c < NC; ++c) {
        if (c + 1 < NC) asm volatile("cp.async.wait_group 1;" ::: "memory");
        else            asm volatile("cp.async.wait_group 0;" ::: "memory");
        __syncthreads();

        const uint32_t sbase = sb + (uint32_t)(c % STAGES) * G_STAGE;
        const int cn = c + 2;
        const uint32_t nbase = sb + (uint32_t)(cn % STAGES) * G_STAGE;
        const bool has_next = cn < NC;

        ld_frag(0, sbase, 0);
        #pragma unroll
        for (int ks = 0; ks < 4; ++ks) {
            if (ks < 3) ld_frag((ks + 1) & 1, sbase, ks + 1);
            if (has_next) load_part(cn, nbase, ks);
            mma_all(ks & 1);
        }
        if (has_next) cp_commit();
    }

    const int tig = l & 3, grp = l >> 2;
    #pragma unroll
    for (int nf = 0; nf < 4; ++nf) {
        const long col = n0 + wn + nf * 8 + 2 * tig;
        const float b0 = bias[col], b1 = bias[col + 1];
        #pragma unroll
        for (int mf = 0; mf < 4; ++mf) {
            const long r0 = m0 + wm + mf * 16 + grp;
            float v00 = acc[mf][nf][0] + b0, v01 = acc[mf][nf][1] + b1;
            float v10 = acc[mf][nf][2] + b0, v11 = acc[mf][nf][3] + b1;
            if (RELU) {
                v00 = fmaxf(v00, 0.f); v01 = fmaxf(v01, 0.f);
                v10 = fmaxf(v10, 0.f); v11 = fmaxf(v11, 0.f);
            }
            if (OUT16) {
                *reinterpret_cast<uint32_t*>(Ch + r0 * (long)ldc + col) = pack_h2(v00, v01);
                *reinterpret_cast<uint32_t*>(Ch + (r0 + 8) * (long)ldc + col) = pack_h2(v10, v11);
            } else {
                *reinterpret_cast<float2*>(Cf + r0 * (long)ldc + col) = make_float2(v00, v01);
                *reinterpret_cast<float2*>(Cf + (r0 + 8) * (long)ldc + col) = make_float2(v10, v11);
            }
        }
    }
}

// ---------------------------------------------------------------------------
// Launch
// ---------------------------------------------------------------------------
extern "C" void kernel_launch(void* const* d_in, const int* in_sizes, int n_in,
                              void* d_out, int out_size)
{
    const int*   ids   = (const int*)  d_in[0];
    const float* table = (const float*)d_in[1];
    const float* en_g  = (const float*)d_in[2];
    const float* en_b  = (const float*)d_in[3];
    const float* Wb    = (const float*)d_in[4];
    const float* bb    = (const float*)d_in[5];
    const float* cn_g  = (const float*)d_in[6];
    const float* cn_b  = (const float*)d_in[7];
    const float* tn_g  = (const float*)d_in[8];
    const float* tn_b  = (const float*)d_in[9];
    const float* out_W = (const float*)d_in[10];
    const float* out_b = (const float*)d_in[11];
    float* logits = (float*)d_out;

    __half *xh, *yh, *wh, *owh;
    float *h2;
    cudaGetSymbolAddress((void**)&xh,  g_xh);
    cudaGetSymbolAddress((void**)&yh,  g_yh);
    cudaGetSymbolAddress((void**)&wh,  g_wh);
    cudaGetSymbolAddress((void**)&owh, g_owh);
    cudaGetSymbolAddress((void**)&h2,  g_h2);

    cudaFuncSetAttribute((const void*)gemm_f16<true, true>,
                         cudaFuncAttributeMaxDynamicSharedMemorySize, G_SMEM);
    cudaFuncSetAttribute((const void*)gemm_f16<true, false>,
                         cudaFuncAttributeMaxDynamicSharedMemorySize, G_SMEM);
    cudaFuncSetAttribute((const void*)gemm_f16<false, false>,
                         cudaFuncAttributeMaxDynamicSharedMemorySize, G_SMEM);

    // 1) weights -> fp16
    f32_to_f16<<<W_ELEMS / 4 / 256, 256>>>(
        (const float4*)Wb, (uint2*)wh, W_ELEMS / 4);
    f32_to_f16<<<OW_ELEMS / 4 / 256, 256>>>(
        (const float4*)out_W, (uint2*)owh, OW_ELEMS / 4);

    // 2) embedding + LN
    embed_ln_kernel<<<NTOK, 128>>>(ids, table, en_g, en_b);

    // 3) three residual blocks (single-term fp16 FNN)
    const dim3 fnn_grid(H / BN, NTOK / BM);           // (8, 32)
    for (int bi = 0; bi < 3; ++bi) {
        const __half* W0 = wh + (long)(bi * 2 + 0) * H * H;
        const __half* W1 = wh + (long)(bi * 2 + 1) * H * H;
        const float* b0 = bb + (bi * 2 + 0) * H;
        const float* b1 = bb + (bi * 2 + 1) * H;

        gemm_f16<true, true><<<fnn_grid, 256, G_SMEM>>>(
            xh, H, W0, H, b0, (float*)nullptr, yh, H, H);
        gemm_f16<true, false><<<fnn_grid, 256, G_SMEM>>>(
            yh, H, W1, H, b1, h2, (__half*)nullptr, H, H);
        resid_ln_kernel<<<dim3(NTOK, 2), 128>>>(cn_g + bi * C, cn_b + bi * C,
                                                tn_g + bi * E, tn_b + bi * E);
    }

    // 4) logits = tok @ out_W^T + out_b  (A = xh[:, C:] fp16)
    const dim3 out_grid(V / BN, NTOK / BM);           // (250, 32)
    gemm_f16<false, false><<<out_grid, 256, G_SMEM>>>(
        xh + C, H, owh, C, out_b, logits, (__half*)nullptr, V, C);
}

// round 11
// speedup vs baseline: 2.4881x; 1.0438x over previous
#include <cuda_runtime.h>
#include <cuda_fp16.h>
#include <cstdint>

// Problem constants (fixed by the dataset)
constexpr int NTOK = 4096;      // B*S = 4*1024
constexpr int E    = 512;
constexpr int C    = 512;
constexpr int H    = 1024;
constexpr int V    = 32000;
constexpr float EPS = 1e-5f;

constexpr int W_ELEMS  = 3 * 2 * H * H;
constexpr int OW_ELEMS = V * C;

// Tiling: 128x128x64, 256 threads, warp 64x32. Stage = A|B fp16 tiles.
constexpr int BM = 128, BN = 128, BK = 64;
constexpr int TILE16  = BM * BK * 2;              // 16384 bytes per fp16 tile
constexpr int STAGES  = 3;
constexpr int G_STAGE = 2 * TILE16;               // 32768
constexpr int G_SMEM  = STAGES * G_STAGE;         // 98304 -> 2 CTAs/SM (192KB<=227KB)

// Scratch (allocation-free rule: __device__ globals)
__device__ float g_hbuf[NTOK * H];                // fp32 residual state [ctx|tok]
__device__ float g_h2[NTOK * H];                  // fp32 FNN block output
__device__ __half g_xh[NTOK * H];                 // x fp16 (GEMM-1 in; xh[:,C:] = logits A)
__device__ __half g_yh[NTOK * H];                 // GEMM-2 input fp16
__device__ __half g_wh[W_ELEMS];                  // FNN weights fp16
__device__ __half g_owh[OW_ELEMS];                // out_W fp16

// ---------------------------------------------------------------------------
// PTX helpers
// ---------------------------------------------------------------------------
__device__ __forceinline__ uint32_t cvta_smem(const void* p) {
    uint32_t a;
    asm("{\n\t.reg .u64 t;\n\tcvta.to.shared.u64 t, %1;\n\tcvt.u32.u64 %0, t;\n\t}"
        : "=r"(a) : "l"(p));
    return a;
}
__device__ __forceinline__ uint32_t swz(uint32_t o) { return o ^ ((o >> 3) & 0x70); }

__device__ __forceinline__ void cp16(uint32_t dst, const void* src) {
    asm volatile("cp.async.cg.shared.global [%0], [%1], 16;" :: "r"(dst), "l"(src));
}
__device__ __forceinline__ void cp_commit() {
    asm volatile("cp.async.commit_group;" ::: "memory");
}

__device__ __forceinline__ void ldsm4(uint32_t* r, uint32_t addr) {
    asm volatile("ldmatrix.sync.aligned.m8n8.x4.shared.b16 {%0,%1,%2,%3}, [%4];"
                 : "=r"(r[0]), "=r"(r[1]), "=r"(r[2]), "=r"(r[3]) : "r"(addr));
}

__device__ __forceinline__ void mma16816h(float* d, const uint32_t* a,
                                          uint32_t b0, uint32_t b1) {
    asm("mma.sync.aligned.m16n8k16.row.col.f32.f16.f16.f32 "
        "{%0,%1,%2,%3}, {%4,%5,%6,%7}, {%8,%9}, {%0,%1,%2,%3};"
        : "+f"(d[0]), "+f"(d[1]), "+f"(d[2]), "+f"(d[3])
        : "r"(a[0]), "r"(a[1]), "r"(a[2]), "r"(a[3]), "r"(b0), "r"(b1));
}

__device__ __forceinline__ uint32_t pack_h2(float a, float b) {
    return (uint32_t)__half_as_ushort(__float2half_rn(a)) |
           ((uint32_t)__half_as_ushort(__float2half_rn(b)) << 16);
}

// ---------------------------------------------------------------------------
// fp32 -> fp16 (weights)
// ---------------------------------------------------------------------------
__global__ void __launch_bounds__(256) f32_to_f16(
    const float4* __restrict__ src, uint2* __restrict__ dst, int n4)
{
    const int i = blockIdx.x * 256 + threadIdx.x;
    if (i >= n4) return;
    const float4 x = src[i];
    dst[i] = make_uint2(pack_h2(x.x, x.y), pack_h2(x.z, x.w));
}

// ---------------------------------------------------------------------------
// LN reduction helper (128 threads = 4 warps)
// ---------------------------------------------------------------------------
__device__ __forceinline__ void block_reduce_2(float& s, float& s2) {
    #pragma unroll
    for (int o = 16; o > 0; o >>= 1) {
        s  += __shfl_xor_sync(0xFFFFFFFFu, s,  o);
        s2 += __shfl_xor_sync(0xFFFFFFFFu, s2, o);
    }
    __shared__ float red[8];
    int wid = threadIdx.x >> 5;
    int lid = threadIdx.x & 31;
    if (lid == 0) { red[wid] = s; red[4 + wid] = s2; }
    __syncthreads();
    s  = red[0] + red[1] + red[2] + red[3];
    s2 = red[4] + red[5] + red[6] + red[7];
}

// ---------------------------------------------------------------------------
// Embedding gather + LN -> hbuf fp32 [0|tok] and x fp16 (full row)
// ---------------------------------------------------------------------------
__global__ void __launch_bounds__(128) embed_ln_kernel(
    const int* __restrict__ ids, const float* __restrict__ table,
    const float* __restrict__ g, const float* __restrict__ b)
{
    const int tok = blockIdx.x;
    const int tid = threadIdx.x;
    const long id = ids[tok];

    float4 x = reinterpret_cast<const float4*>(table + id * (long)E)[tid];
    float s  = x.x + x.y + x.z + x.w;
    float s2 = x.x * x.x + x.y * x.y + x.z * x.z + x.w * x.w;
    block_reduce_2(s, s2);

    const float mean = s * (1.0f / E);
    const float var  = s2 * (1.0f / E) - mean * mean;
    const float rstd = rsqrtf(var + EPS);

    float4 gg = reinterpret_cast<const float4*>(g)[tid];
    float4 bb = reinterpret_cast<const float4*>(b)[tid];
    float4 y;
    y.x = (x.x - mean) * rstd * gg.x + bb.x;
    y.y = (x.y - mean) * rstd * gg.y + bb.y;
    y.z = (x.z - mean) * rstd * gg.z + bb.z;
    y.w = (x.w - mean) * rstd * gg.w + bb.w;

    const long rbase = (long)tok * H;
    float* row = g_hbuf + rbase;
    reinterpret_cast<float4*>(row + C)[tid] = y;
    reinterpret_cast<float4*>(row)[tid] = make_float4(0.f, 0.f, 0.f, 0.f);

    reinterpret_cast<uint2*>(g_xh + rbase + C)[tid] =
        make_uint2(pack_h2(y.x, y.y), pack_h2(y.z, y.w));
    reinterpret_cast<uint2*>(g_xh + rbase)[tid] = make_uint2(0, 0);
}

// ---------------------------------------------------------------------------
// Residual + LN; writes hbuf fp32 and x fp16
// ---------------------------------------------------------------------------
__global__ void __launch_bounds__(128) resid_ln_kernel(
    const float* __restrict__ cg, const float* __restrict__ cb,
    const float* __restrict__ tg, const float* __restrict__ tb)
{
    const int tok  = blockIdx.x;
    const int half = blockIdx.y;
    const int tid  = threadIdx.x;
    const float* g  = half ? tg : cg;
    const float* bp = half ? tb : cb;

    const long base = (long)tok * H + half * C;
    float4 a = reinterpret_cast<const float4*>(g_hbuf + base)[tid];
    float4 h = reinterpret_cast<const float4*>(g_h2 + base)[tid];
    float4 x;
    x.x = a.x + h.x; x.y = a.y + h.y; x.z = a.z + h.z; x.w = a.w + h.w;

    float s  = x.x + x.y + x.z + x.w;
    float s2 = x.x * x.x + x.y * x.y + x.z * x.z + x.w * x.w;
    block_reduce_2(s, s2);

    const float mean = s * (1.0f / C);
    const float var  = s2 * (1.0f / C) - mean * mean;
    const float rstd = rsqrtf(var + EPS);

    float4 gg = reinterpret_cast<const float4*>(g)[tid];
    float4 bb = reinterpret_cast<const float4*>(bp)[tid];
    float4 y;
    y.x = (x.x - mean) * rstd * gg.x + bb.x;
    y.y = (x.y - mean) * rstd * gg.y + bb.y;
    y.z = (x.z - mean) * rstd * gg.z + bb.z;
    y.w = (x.w - mean) * rstd * gg.w + bb.w;
    reinterpret_cast<float4*>(g_hbuf + base)[tid] = y;

    reinterpret_cast<uint2*>(g_xh + base)[tid] =
        make_uint2(pack_h2(y.x, y.y), pack_h2(y.z, y.w));
}

// ---------------------------------------------------------------------------
// Unified single-term fp16 GEMM: D = A @ B^T + bias, fp32 accumulate.
// __launch_bounds__(256, 2): 2 CTAs/SM (96KB smem each, regs capped at 128).
// Single-buffered fragments (double-buffering measured neutral R4/R5; the
// freed 24 regs buy the occupancy). 3-stage cp.async pipeline, SW128 swizzle.
// ---------------------------------------------------------------------------
template <bool RELU, bool OUT16>
__global__ void __launch_bounds__(256, 2) gemm_f16(
    const __half* __restrict__ A, int lda,
    const __half* __restrict__ B, int ldb,
    const float* __restrict__ bias,
    float* __restrict__ Cf, __half* __restrict__ Ch,
    int ldc, int K)
{
    extern __shared__ char smem[];
    const uint32_t sb = cvta_smem(smem);
    const int tid = threadIdx.x;
    const int w   = tid >> 5;
    const int l   = tid & 31;
    const int wm  = (w >> 2) * 64;
    const int wn  = (w & 3) * 32;
    const long m0 = (long)blockIdx.y * BM;
    const long n0 = (long)blockIdx.x * BN;

    const int lrow  = ((l >> 3) & 1) * 8 + (l & 7);
    const int lkseg = ((l >> 4) & 1) * 16;

    const int NC = K >> 6;

    const int ldr  = tid >> 3;
    const int ldc8 = (tid & 7) * 8;

    auto load_part = [&](int c, uint32_t sbase, int it) {
        const int k0 = c << 6;
        const int r = it * 32 + ldr;
        const uint32_t so = swz((uint32_t)(r * 128) + (uint32_t)((tid & 7) * 16));
        const long ga = (m0 + r) * (long)lda + k0 + ldc8;
        const long gb = (n0 + r) * (long)ldb + k0 + ldc8;
        cp16(sbase + so,          A + ga);
        cp16(sbase + TILE16 + so, B + gb);
    };
    auto load_chunk = [&](int c, int stage) {
        const uint32_t sbase = sb + (uint32_t)stage * G_STAGE;
        #pragma unroll
        for (int it = 0; it < 4; ++it) load_part(c, sbase, it);
    };

    float acc[4][4][4];
    #pragma unroll
    for (int i = 0; i < 4; ++i)
        #pragma unroll
        for (int j = 0; j < 4; ++j)
            #pragma unroll
            for (int q = 0; q < 4; ++q) acc[i][j][q] = 0.0f;

    // single-buffered fragments — occupancy (4 warps/SMSP) covers ldsm latency
    uint32_t Af[4][4], Bf[2][4];

    auto ld_frag = [&](uint32_t sbase, int ks) {
        const int kb = ks * 32 + lkseg;
        #pragma unroll
        for (int mf = 0; mf < 4; ++mf) {
            const uint32_t off = swz((uint32_t)((wm + mf * 16 + lrow) * 128 + kb));
            ldsm4(Af[mf], sbase + off);
        }
        #pragma unroll
        for (int nf2 = 0; nf2 < 2; ++nf2) {
            const uint32_t off = swz((uint32_t)((wn + nf2 * 16 + lrow) * 128 + kb));
            ldsm4(Bf[nf2], sbase + TILE16 + off);
        }
    };
    auto mma_all = [&]() {
        #pragma unroll
        for (int mf = 0; mf < 4; ++mf)
            #pragma unroll
            for (int nf = 0; nf < 4; ++nf) {
                const int p = nf >> 1, q = nf & 1;
                mma16816h(acc[mf][nf], Af[mf], Bf[p][q], Bf[p][q + 2]);
            }
    };

    load_chunk(0, 0); cp_commit();
    if (NC > 1) { load_chunk(1, 1); cp_commit(); }

    for (int c = 0; c < NC; ++c) {
        if (c + 1 < NC) asm volatile("cp.async.wait_group 1;" ::: "memory");
        else            asm volatile("cp.async.wait_group 0;" ::: "memory");
        __syncthreads();

        const uint32_t sbase = sb + (uint32_t)(c % STAGES) * G_STAGE;
        const int cn = c + 2;
        const uint32_t nbase = sb + (uint32_t)(cn % STAGES) * G_STAGE;
        const bool has_next = cn < NC;

        #pragma unroll
        for (int ks = 0; ks < 4; ++ks) {
            ld_frag(sbase, ks);
            if (has_next) load_part(cn, nbase, ks);
            mma_all();
        }
        if (has_next) cp_commit();
    }

    const int tig = l & 3, grp = l >> 2;
    #pragma unroll
    for (int nf = 0; nf < 4; ++nf) {
        const long col = n0 + wn + nf * 8 + 2 * tig;
        const float b0 = bias[col], b1 = bias[col + 1];
        #pragma unroll
        for (int mf = 0; mf < 4; ++mf) {
            const long r0 = m0 + wm + mf * 16 + grp;
            float v00 = acc[mf][nf][0] + b0, v01 = acc[mf][nf][1] + b1;
            float v10 = acc[mf][nf][2] + b0, v11 = acc[mf][nf][3] + b1;
            if (RELU) {
                v00 = fmaxf(v00, 0.f); v01 = fmaxf(v01, 0.f);
                v10 = fmaxf(v10, 0.f); v11 = fmaxf(v11, 0.f);
            }
            if (OUT16) {
                *reinterpret_cast<uint32_t*>(Ch + r0 * (long)ldc + col) = pack_h2(v00, v01);
                *reinterpret_cast<uint32_t*>(Ch + (r0 + 8) * (long)ldc + col) = pack_h2(v10, v11);
            } else {
                *reinterpret_cast<float2*>(Cf + r0 * (long)ldc + col) = make_float2(v00, v01);
                *reinterpret_cast<float2*>(Cf + (r0 + 8) * (long)ldc + col) = make_float2(v10, v11);
            }
        }
    }
}

// ---------------------------------------------------------------------------
// Launch
// ---------------------------------------------------------------------------
extern "C" void kernel_launch(void* const* d_in, const int* in_sizes, int n_in,
                              void* d_out, int out_size)
{
    const int*   ids   = (const int*)  d_in[0];
    const float* table = (const float*)d_in[1];
    const float* en_g  = (const float*)d_in[2];
    const float* en_b  = (const float*)d_in[3];
    const float* Wb    = (const float*)d_in[4];
    const float* bb    = (const float*)d_in[5];
    const float* cn_g  = (const float*)d_in[6];
    const float* cn_b  = (const float*)d_in[7];
    const float* tn_g  = (const float*)d_in[8];
    const float* tn_b  = (const float*)d_in[9];
    const float* out_W = (const float*)d_in[10];
    const float* out_b = (const float*)d_in[11];
    float* logits = (float*)d_out;

    __half *xh, *yh, *wh, *owh;
    float *h2;
    cudaGetSymbolAddress((void**)&xh,  g_xh);
    cudaGetSymbolAddress((void**)&yh,  g_yh);
    cudaGetSymbolAddress((void**)&wh,  g_wh);
    cudaGetSymbolAddress((void**)&owh, g_owh);
    cudaGetSymbolAddress((void**)&h2,  g_h2);

    cudaFuncSetAttribute((const void*)gemm_f16<true, true>,
                         cudaFuncAttributeMaxDynamicSharedMemorySize, G_SMEM);
    cudaFuncSetAttribute((const void*)gemm_f16<true, false>,
                         cudaFuncAttributeMaxDynamicSharedMemorySize, G_SMEM);
    cudaFuncSetAttribute((const void*)gemm_f16<false, false>,
                         cudaFuncAttributeMaxDynamicSharedMemorySize, G_SMEM);

    // 1) weights -> fp16
    f32_to_f16<<<W_ELEMS / 4 / 256, 256>>>(
        (const float4*)Wb, (uint2*)wh, W_ELEMS / 4);
    f32_to_f16<<<OW_ELEMS / 4 / 256, 256>>>(
        (const float4*)out_W, (uint2*)owh, OW_ELEMS / 4);

    // 2) embedding + LN
    embed_ln_kernel<<<NTOK, 128>>>(ids, table, en_g, en_b);

    // 3) three residual blocks (single-term fp16 FNN)
    const dim3 fnn_grid(H / BN, NTOK / BM);           // (8, 32) = 256 CTAs, all resident at occ 2
    for (int bi = 0; bi < 3; ++bi) {
        const __half* W0 = wh + (long)(bi * 2 + 0) * H * H;
        const __half* W1 = wh + (long)(bi * 2 + 1) * H * H;
        const float* b0 = bb + (bi * 2 + 0) * H;
        const float* b1 = bb + (bi * 2 + 1) * H;

        gemm_f16<true, true><<<fnn_grid, 256, G_SMEM>>>(
            xh, H, W0, H, b0, (float*)nullptr, yh, H, H);
        gemm_f16<true, false><<<fnn_grid, 256, G_SMEM>>>(
            yh, H, W1, H, b1, h2, (__half*)nullptr, H, H);
        resid_ln_kernel<<<dim3(NTOK, 2), 128>>>(cn_g + bi * C, cn_b + bi * C,
                                                tn_g + bi * E, tn_b + bi * E);
    }

    // 4) logits = tok @ out_W^T + out_b  (A = xh[:, C:] fp16)
    const dim3 out_grid(V / BN, NTOK / BM);           // (250, 32)
    gemm_f16<false, false><<<out_grid, 256, G_SMEM>>>(
        xh + C, H, owh, C, out_b, logits, (__half*)nullptr, V, C);
}